// round 1
// baseline (speedup 1.0000x reference)
#include <cuda_runtime.h>
#include <math_constants.h>
#include <cstdint>
#include <cstddef>

// ---------------------------------------------------------------------------
// Problem constants
//   B=8, N=8192 media tokens, S=64 latents, DIM=512, HEADS=8, DIM_HEAD=64,
//   INNER=512, SLICE=256, SCALE=0.125, EPS=1e-5
// ---------------------------------------------------------------------------
#define BATCH   8
#define NMEDIA  8192
#define SLAT    64
#define DIMC    512
#define HEADS   8
#define DHEAD   64
#define INNERC  512
#define NSPLIT  33        // 32 media splits of 256 tokens + 1 latent split
#define KC      32        // GEMM k-chunk

// ---------------------------------------------------------------------------
// Scratch (device globals: allocation-free, graph-capture safe)
// ---------------------------------------------------------------------------
__device__ float g_q     [(size_t)BATCH * SLAT * INNERC];          // scaled q
__device__ float g_kvlat [(size_t)BATCH * SLAT * 2 * INNERC];      // [k|v] latents
__device__ float g_kvmed [(size_t)BATCH * NMEDIA * 2 * INNERC];    // [k|v] media (visible only)
__device__ float g_opart [(size_t)BATCH * HEADS * NSPLIT * SLAT * DHEAD];
__device__ float g_mpart [(size_t)BATCH * HEADS * NSPLIT * SLAT];
__device__ float g_lpart [(size_t)BATCH * HEADS * NSPLIT * SLAT];
__device__ float g_attno [(size_t)BATCH * SLAT * INNERC];

// ---------------------------------------------------------------------------
// Fused LayerNorm + GEMM:  out[b, rowBase+i, colBase+j] =
//     ( sum_k LN(src[b, rowBase+i, k]) * W[k, colBase+j] + bias[colBase+j] ) * outScale
// gln == nullptr -> no LN (plain GEMM). indices != nullptr -> skip row-tiles
// with rowBase >= indices[b]*256 (visibility mask; 256 is a multiple of 64).
// 64x64 tile, 256 threads, 4x4 per-thread micro-tile.
// ---------------------------------------------------------------------------
__global__ void __launch_bounds__(256)
fused_ln_gemm(const float* __restrict__ src, int T,
              const float* __restrict__ gln, const float* __restrict__ bln,
              const float* __restrict__ W, int ldw,
              const float* __restrict__ bias, float outScale,
              float* __restrict__ out, int ldo,
              const int* __restrict__ indices)
{
    const int b = blockIdx.z;
    const int rowBase = blockIdx.y * 64;
    const int colBase = blockIdx.x * 64;
    if (indices) {
        if (rowBase >= indices[b] * 256) return;   // fully masked token tile
    }
    const float* srcB = src + ((size_t)b * T + rowBase) * DIMC;

    __shared__ __align__(16) float As[KC][68];
    __shared__ __align__(16) float Bs[KC][68];
    __shared__ float mu_s[64], rs_s[64];

    const int tid = threadIdx.x;

    // ---- LayerNorm statistics for this 64-row tile ----
    if (gln) {
        const int warp = tid >> 5, lane = tid & 31;
        for (int i = warp; i < 64; i += 8) {
            const float* row = srcB + (size_t)i * DIMC;
            float sum = 0.f, sq = 0.f;
            #pragma unroll 4
            for (int k = lane; k < DIMC; k += 32) {
                float v = row[k];
                sum += v;
                sq  = fmaf(v, v, sq);
            }
            #pragma unroll
            for (int o = 16; o > 0; o >>= 1) {
                sum += __shfl_down_sync(0xffffffffu, sum, o);
                sq  += __shfl_down_sync(0xffffffffu, sq,  o);
            }
            if (lane == 0) {
                float mu  = sum * (1.f / 512.f);
                float var = fmaf(-mu, mu, sq * (1.f / 512.f));
                mu_s[i] = mu;
                rs_s[i] = rsqrtf(var + 1e-5f);
            }
        }
    }
    __syncthreads();

    const int tx = tid & 15, ty = tid >> 4;
    float acc[4][4] = {};

    for (int k0 = 0; k0 < DIMC; k0 += KC) {
        // ---- stage A tile (k-major in smem), LN applied on the fly ----
        #pragma unroll
        for (int it = 0; it < 2; ++it) {
            int e  = tid + it * 256;       // 0..511 float4 slots
            int r  = e >> 3;               // token row 0..63
            int kk = (e & 7) * 4;          // k offset 0..28
            float4 v = *(const float4*)(srcB + (size_t)r * DIMC + k0 + kk);
            if (gln) {
                float mu = mu_s[r], rs = rs_s[r];
                As[kk + 0][r] = fmaf((v.x - mu) * rs, gln[k0 + kk + 0], bln[k0 + kk + 0]);
                As[kk + 1][r] = fmaf((v.y - mu) * rs, gln[k0 + kk + 1], bln[k0 + kk + 1]);
                As[kk + 2][r] = fmaf((v.z - mu) * rs, gln[k0 + kk + 2], bln[k0 + kk + 2]);
                As[kk + 3][r] = fmaf((v.w - mu) * rs, gln[k0 + kk + 3], bln[k0 + kk + 3]);
            } else {
                As[kk + 0][r] = v.x;
                As[kk + 1][r] = v.y;
                As[kk + 2][r] = v.z;
                As[kk + 3][r] = v.w;
            }
        }
        // ---- stage B tile ----
        #pragma unroll
        for (int it = 0; it < 2; ++it) {
            int e = tid + it * 256;
            int r = e >> 4;                // k row 0..31
            int c = (e & 15) * 4;          // col 0..60
            float4 v = *(const float4*)(W + (size_t)(k0 + r) * ldw + colBase + c);
            Bs[r][c + 0] = v.x;
            Bs[r][c + 1] = v.y;
            Bs[r][c + 2] = v.z;
            Bs[r][c + 3] = v.w;
        }
        __syncthreads();

        #pragma unroll
        for (int kk = 0; kk < KC; ++kk) {
            float4 a4 = *(const float4*)&As[kk][ty * 4];
            float4 b4 = *(const float4*)&Bs[kk][tx * 4];
            float a[4] = {a4.x, a4.y, a4.z, a4.w};
            float bb[4] = {b4.x, b4.y, b4.z, b4.w};
            #pragma unroll
            for (int r = 0; r < 4; ++r)
                #pragma unroll
                for (int c = 0; c < 4; ++c)
                    acc[r][c] = fmaf(a[r], bb[c], acc[r][c]);
        }
        __syncthreads();
    }

    // ---- epilogue: bias + scale ----
    #pragma unroll
    for (int r = 0; r < 4; ++r) {
        int row = rowBase + ty * 4 + r;
        float* orow = out + ((size_t)b * T + row) * ldo;
        #pragma unroll
        for (int c = 0; c < 4; ++c) {
            int col = colBase + tx * 4 + c;
            orow[col] = (acc[r][c] + bias[col]) * outScale;
        }
    }
}

// ---------------------------------------------------------------------------
// Split-KV flash attention.
// grid = (33, HEADS, BATCH). Split s<32: media tokens [s*256,(s+1)*256),
// visible iff s < indices[b] (mask slice == split). Split 32: 64 latent keys.
// Per split: online softmax over 64-key chunks, unnormalized output + (m, l)
// partials written to scratch.
// ---------------------------------------------------------------------------
__global__ void __launch_bounds__(256)
attn_split(const float* __restrict__ q, const int* __restrict__ indices)
{
    const int b = blockIdx.z, h = blockIdx.y, s = blockIdx.x;
    const int vis = indices[b];
    const bool is_lat = (s == 32);
    if (!is_lat && s >= vis) return;

    extern __shared__ float smdyn[];
    float* qs  = smdyn;                 // [64][64]   row-major (broadcast reads)
    float* Kt  = qs  + 64 * 64;         // [64][65]   d-major: Kt[d*65 + j]
    float* Vs  = Kt  + 64 * 65;         // [64][65]   j-major: Vs[j*65 + d]
    float* Ss  = Vs  + 64 * 65;         // [64][65]   scores / probabilities
    float* m_s = Ss  + 64 * 65;
    float* l_s = m_s + 64;
    float* c_s = l_s + 64;

    const int tid = threadIdx.x;

    // load q tile [64 queries][64 dims] for this (b, h)
    #pragma unroll
    for (int it = 0; it < 16; ++it) {
        int e = tid + it * 256;
        int r = e >> 6, c = e & 63;
        qs[r * 64 + c] = q[((size_t)b * SLAT + r) * INNERC + h * DHEAD + c];
    }
    if (tid < 64) { m_s[tid] = -CUDART_INF_F; l_s[tid] = 0.f; }

    const float* kvbase = is_lat
        ? (g_kvlat + (size_t)b * SLAT * 1024)
        : (g_kvmed + ((size_t)b * NMEDIA + (size_t)s * 256) * 1024);
    const int nch = is_lat ? 1 : 4;

    const int tx = tid & 15, ty = tid >> 4;
    float o[4][4] = {};

    for (int ch = 0; ch < nch; ++ch) {
        __syncthreads();   // previous chunk's Ss/Vs consumed; q/m/l ready (iter 0)
        // ---- load K (transposed) and V chunk ----
        #pragma unroll
        for (int it = 0; it < 16; ++it) {
            int e = tid + it * 256;
            int j = e >> 6, d = e & 63;
            const float* rp = kvbase + (size_t)(ch * 64 + j) * 1024 + h * DHEAD;
            Kt[d * 65 + j] = rp[d];
            Vs[j * 65 + d] = rp[512 + d];
        }
        __syncthreads();

        // ---- S = q @ K^T (64x64x64) ----
        float sacc[4][4] = {};
        #pragma unroll 8
        for (int d = 0; d < 64; ++d) {
            float a0 = qs[(ty * 4 + 0) * 64 + d];
            float a1 = qs[(ty * 4 + 1) * 64 + d];
            float a2 = qs[(ty * 4 + 2) * 64 + d];
            float a3 = qs[(ty * 4 + 3) * 64 + d];
            float b0 = Kt[d * 65 + tx * 4 + 0];
            float b1 = Kt[d * 65 + tx * 4 + 1];
            float b2 = Kt[d * 65 + tx * 4 + 2];
            float b3 = Kt[d * 65 + tx * 4 + 3];
            sacc[0][0] = fmaf(a0, b0, sacc[0][0]); sacc[0][1] = fmaf(a0, b1, sacc[0][1]);
            sacc[0][2] = fmaf(a0, b2, sacc[0][2]); sacc[0][3] = fmaf(a0, b3, sacc[0][3]);
            sacc[1][0] = fmaf(a1, b0, sacc[1][0]); sacc[1][1] = fmaf(a1, b1, sacc[1][1]);
            sacc[1][2] = fmaf(a1, b2, sacc[1][2]); sacc[1][3] = fmaf(a1, b3, sacc[1][3]);
            sacc[2][0] = fmaf(a2, b0, sacc[2][0]); sacc[2][1] = fmaf(a2, b1, sacc[2][1]);
            sacc[2][2] = fmaf(a2, b2, sacc[2][2]); sacc[2][3] = fmaf(a2, b3, sacc[2][3]);
            sacc[3][0] = fmaf(a3, b0, sacc[3][0]); sacc[3][1] = fmaf(a3, b1, sacc[3][1]);
            sacc[3][2] = fmaf(a3, b2, sacc[3][2]); sacc[3][3] = fmaf(a3, b3, sacc[3][3]);
        }
        #pragma unroll
        for (int r = 0; r < 4; ++r)
            #pragma unroll
            for (int c = 0; c < 4; ++c)
                Ss[(ty * 4 + r) * 65 + tx * 4 + c] = sacc[r][c];
        __syncthreads();

        // ---- online softmax row update (threads 0..63, one row each) ----
        if (tid < 64) {
            const int i = tid;
            float rm = -CUDART_INF_F;
            #pragma unroll 8
            for (int j = 0; j < 64; ++j) rm = fmaxf(rm, Ss[i * 65 + j]);
            float mo = m_s[i];
            float mn = fmaxf(mo, rm);
            float cc = __expf(mo - mn);    // 0 on first chunk (mo = -inf)
            float sum = 0.f;
            #pragma unroll 8
            for (int j = 0; j < 64; ++j) {
                float p = __expf(Ss[i * 65 + j] - mn);
                Ss[i * 65 + j] = p;
                sum += p;
            }
            m_s[i] = mn;
            l_s[i] = fmaf(l_s[i], cc, sum);
            c_s[i] = cc;
        }
        __syncthreads();

        // ---- o = o * c + P @ V ----
        float c0 = c_s[ty * 4 + 0], c1 = c_s[ty * 4 + 1];
        float c2 = c_s[ty * 4 + 2], c3 = c_s[ty * 4 + 3];
        #pragma unroll
        for (int c = 0; c < 4; ++c) {
            o[0][c] *= c0; o[1][c] *= c1; o[2][c] *= c2; o[3][c] *= c3;
        }
        #pragma unroll 8
        for (int j = 0; j < 64; ++j) {
            float p0 = Ss[(ty * 4 + 0) * 65 + j];
            float p1 = Ss[(ty * 4 + 1) * 65 + j];
            float p2 = Ss[(ty * 4 + 2) * 65 + j];
            float p3 = Ss[(ty * 4 + 3) * 65 + j];
            float v0 = Vs[j * 65 + tx * 4 + 0];
            float v1 = Vs[j * 65 + tx * 4 + 1];
            float v2 = Vs[j * 65 + tx * 4 + 2];
            float v3 = Vs[j * 65 + tx * 4 + 3];
            o[0][0] = fmaf(p0, v0, o[0][0]); o[0][1] = fmaf(p0, v1, o[0][1]);
            o[0][2] = fmaf(p0, v2, o[0][2]); o[0][3] = fmaf(p0, v3, o[0][3]);
            o[1][0] = fmaf(p1, v0, o[1][0]); o[1][1] = fmaf(p1, v1, o[1][1]);
            o[1][2] = fmaf(p1, v2, o[1][2]); o[1][3] = fmaf(p1, v3, o[1][3]);
            o[2][0] = fmaf(p2, v0, o[2][0]); o[2][1] = fmaf(p2, v1, o[2][1]);
            o[2][2] = fmaf(p2, v2, o[2][2]); o[2][3] = fmaf(p2, v3, o[2][3]);
            o[3][0] = fmaf(p3, v0, o[3][0]); o[3][1] = fmaf(p3, v1, o[3][1]);
            o[3][2] = fmaf(p3, v2, o[3][2]); o[3][3] = fmaf(p3, v3, o[3][3]);
        }
    }

    // ---- write partials ----
    const size_t pbase = ((size_t)(b * HEADS + h)) * NSPLIT + s;
    float* op = g_opart + pbase * (SLAT * DHEAD);
    #pragma unroll
    for (int r = 0; r < 4; ++r)
        #pragma unroll
        for (int c = 0; c < 4; ++c)
            op[(ty * 4 + r) * DHEAD + tx * 4 + c] = o[r][c];
    if (tid < 64) {
        g_mpart[pbase * SLAT + tid] = m_s[tid];
        g_lpart[pbase * SLAT + tid] = l_s[tid];
    }
}

// ---------------------------------------------------------------------------
// Combine split partials -> attn_out [B][S][INNER]  (inner index = h*64 + d)
// Only merges visible media splits (s < indices[b]) plus the latent split.
// ---------------------------------------------------------------------------
__global__ void __launch_bounds__(256)
attn_combine(const int* __restrict__ indices, float* __restrict__ attn_out)
{
    const int bh = blockIdx.x;
    const int b = bh >> 3, h = bh & 7;
    const int vis = indices[b];

    __shared__ float w[NSPLIT][64];
    __shared__ float lg[64];

    const int tid = threadIdx.x;
    const size_t base = (size_t)bh * NSPLIT;

    if (tid < 64) {
        const int i = tid;
        float m = g_mpart[(base + 32) * SLAT + i];
        for (int s = 0; s < vis; ++s)
            m = fmaxf(m, g_mpart[(base + s) * SLAT + i]);
        float l = 0.f;
        for (int s = 0; s < vis; ++s) {
            float ww = __expf(g_mpart[(base + s) * SLAT + i] - m);
            w[s][i] = ww;
            l = fmaf(g_lpart[(base + s) * SLAT + i], ww, l);
        }
        {
            float ww = __expf(g_mpart[(base + 32) * SLAT + i] - m);
            w[32][i] = ww;
            l = fmaf(g_lpart[(base + 32) * SLAT + i], ww, l);
        }
        lg[i] = l;
    }
    __syncthreads();

    #pragma unroll
    for (int it = 0; it < 16; ++it) {
        int e = tid + it * 256;           // 0..4095
        int i = e >> 6, d = e & 63;
        float acc = g_opart[(base + 32) * 4096 + e] * w[32][i];
        for (int s = 0; s < vis; ++s)
            acc = fmaf(g_opart[(base + s) * 4096 + e], w[s][i], acc);
        attn_out[((size_t)b * SLAT + i) * INNERC + h * DHEAD + d] = acc / lg[i];
    }
}

// ---------------------------------------------------------------------------
// Launch
// ---------------------------------------------------------------------------
#define ATTN_SMEM ((64 * 64 + 3 * 64 * 65 + 3 * 64) * (int)sizeof(float))

extern "C" void kernel_launch(void* const* d_in, const int* in_sizes, int n_in,
                              void* d_out, int out_size)
{
    (void)in_sizes; (void)n_in; (void)out_size;
    const float* x    = (const float*)d_in[0];
    const float* lat  = (const float*)d_in[1];
    const int*   idx  = (const int*)  d_in[2];
    const float* g_m  = (const float*)d_in[3];
    const float* b_m  = (const float*)d_in[4];
    const float* g_l  = (const float*)d_in[5];
    const float* b_l  = (const float*)d_in[6];
    const float* Wq   = (const float*)d_in[7];
    const float* bq   = (const float*)d_in[8];
    const float* Wkv  = (const float*)d_in[9];
    const float* bkv  = (const float*)d_in[10];
    const float* Wo   = (const float*)d_in[11];
    const float* bo   = (const float*)d_in[12];
    float* out = (float*)d_out;

    void *pq = nullptr, *pkvlat = nullptr, *pkvmed = nullptr, *pattno = nullptr;
    cudaGetSymbolAddress(&pq,     g_q);
    cudaGetSymbolAddress(&pkvlat, g_kvlat);
    cudaGetSymbolAddress(&pkvmed, g_kvmed);
    cudaGetSymbolAddress(&pattno, g_attno);

    cudaFuncSetAttribute(attn_split,
                         cudaFuncAttributeMaxDynamicSharedMemorySize, ATTN_SMEM);

    // q = LN(latents) @ Wq + bq, scaled by DIM_HEAD^-0.5
    fused_ln_gemm<<<dim3(8, 1, 8), 256>>>(lat, SLAT, g_l, b_l,
                                          Wq, 512, bq, 0.125f,
                                          (float*)pq, 512, nullptr);
    // [k|v] for latents = LN(latents) @ Wkv + bkv
    fused_ln_gemm<<<dim3(16, 1, 8), 256>>>(lat, SLAT, g_l, b_l,
                                           Wkv, 1024, bkv, 1.0f,
                                           (float*)pkvlat, 1024, nullptr);
    // [k|v] for VISIBLE media tokens only (mask-skipped at tile level)
    fused_ln_gemm<<<dim3(16, 128, 8), 256>>>(x, NMEDIA, g_m, b_m,
                                             Wkv, 1024, bkv, 1.0f,
                                             (float*)pkvmed, 1024, idx);
    // split-KV attention + combine
    attn_split<<<dim3(NSPLIT, HEADS, BATCH), 256, ATTN_SMEM>>>((const float*)pq, idx);
    attn_combine<<<64, 256>>>(idx, (float*)pattno);
    // output projection: attn_out @ Wo + bo
    fused_ln_gemm<<<dim3(8, 1, 8), 256>>>((const float*)pattno, SLAT, nullptr, nullptr,
                                          Wo, 512, bo, 1.0f,
                                          out, 512, nullptr);
}

// round 2
// speedup vs baseline: 2.6468x; 2.6468x over previous
#include <cuda_runtime.h>
#include <math_constants.h>
#include <cstdint>
#include <cstddef>

// ---------------------------------------------------------------------------
// Problem constants
// ---------------------------------------------------------------------------
#define BATCH   8
#define NMEDIA  8192
#define SLAT    64
#define DIMC    512
#define HEADS   8
#define DHEAD   64
#define INNERC  512
#define NSPLIT  33        // 32 media splits of 256 tokens + 1 latent split

// ---------------------------------------------------------------------------
// Scratch (device globals)
// ---------------------------------------------------------------------------
__device__ float    g_q     [(size_t)BATCH * SLAT * INNERC];
__device__ float    g_kvlat [(size_t)BATCH * SLAT * 2 * INNERC];
__device__ float    g_kvmed [(size_t)BATCH * NMEDIA * 2 * INNERC];
__device__ float    g_opart [(size_t)BATCH * HEADS * NSPLIT * SLAT * DHEAD];
__device__ float    g_mpart [(size_t)BATCH * HEADS * NSPLIT * SLAT];
__device__ float    g_lpart [(size_t)BATCH * HEADS * NSPLIT * SLAT];
__device__ float    g_attno [(size_t)BATCH * SLAT * INNERC];
__device__ float2   g_stat_med[(size_t)BATCH * NMEDIA];
__device__ float2   g_stat_lat[(size_t)BATCH * SLAT];
__device__ uint32_t g_WqT [(size_t)INNERC * DIMC];       // [nc][512] tf32
__device__ uint32_t g_WkvT[(size_t)2 * INNERC * DIMC];
__device__ uint32_t g_WoT [(size_t)DIMC * INNERC];

// ---------------------------------------------------------------------------
// Helpers
// ---------------------------------------------------------------------------
__device__ __forceinline__ uint32_t f2tf32(float x) {
    uint32_t r;
    asm("cvt.rna.tf32.f32 %0, %1;" : "=r"(r) : "f"(x));
    return r;
}

__device__ __forceinline__ void mma_tf32(float* c, const uint32_t* a, const uint32_t* b) {
    asm volatile(
        "mma.sync.aligned.m16n8k8.row.col.f32.tf32.tf32.f32 "
        "{%0,%1,%2,%3},{%4,%5,%6,%7},{%8,%9},{%0,%1,%2,%3};"
        : "+f"(c[0]), "+f"(c[1]), "+f"(c[2]), "+f"(c[3])
        : "r"(a[0]), "r"(a[1]), "r"(a[2]), "r"(a[3]), "r"(b[0]), "r"(b[1]));
}

// ---------------------------------------------------------------------------
// LayerNorm statistics: one warp per row (8 rows / 256-thread block).
// indices != nullptr -> media path with visibility skip (8-row blocks are
// always on one side of the 256-aligned mask boundary).
// ---------------------------------------------------------------------------
__global__ void __launch_bounds__(256)
ln_stats(const float* __restrict__ src, float2* __restrict__ stats,
         const int* __restrict__ indices, int rowsPerBatch)
{
    const int row0 = blockIdx.x * 8;
    if (indices) {
        const int b  = row0 / rowsPerBatch;
        const int lr = row0 % rowsPerBatch;
        if (lr >= indices[b] * 256) return;
    }
    const int warp = threadIdx.x >> 5, lane = threadIdx.x & 31;
    const int row = row0 + warp;
    const float* r = src + (size_t)row * DIMC;
    float s = 0.f, q2 = 0.f;
    #pragma unroll
    for (int u = 0; u < 4; ++u) {
        float4 v = *(const float4*)(r + u * 128 + lane * 4);
        s += v.x + v.y + v.z + v.w;
        q2 = fmaf(v.x, v.x, q2); q2 = fmaf(v.y, v.y, q2);
        q2 = fmaf(v.z, v.z, q2); q2 = fmaf(v.w, v.w, q2);
    }
    #pragma unroll
    for (int o = 16; o > 0; o >>= 1) {
        s  += __shfl_xor_sync(0xffffffffu, s,  o);
        q2 += __shfl_xor_sync(0xffffffffu, q2, o);
    }
    if (lane == 0) {
        float mu  = s * (1.f / 512.f);
        float var = fmaf(-mu, mu, q2 * (1.f / 512.f));
        stats[row] = make_float2(mu, rsqrtf(var + 1e-5f));
    }
}

// ---------------------------------------------------------------------------
// Weight transpose + tf32 convert: W[512][nc] -> WT[nc][512] (tf32 bits).
// Unified across the three weights via blockIdx.z.
// ---------------------------------------------------------------------------
__global__ void __launch_bounds__(256)
transpose_w(const float* __restrict__ Wq, const float* __restrict__ Wkv,
            const float* __restrict__ Wo,
            uint32_t* __restrict__ WqT, uint32_t* __restrict__ WkvT,
            uint32_t* __restrict__ WoT)
{
    const float* W; uint32_t* WT; int nc;
    if      (blockIdx.z == 0) { W = Wq;  WT = WqT;  nc = 512;  }
    else if (blockIdx.z == 1) { W = Wkv; WT = WkvT; nc = 1024; }
    else                      { W = Wo;  WT = WoT;  nc = 512;  }
    const int c0 = blockIdx.x * 64;
    if (c0 >= nc) return;
    const int k0 = blockIdx.y * 64;

    __shared__ float ts[64][65];
    const int tid = threadIdx.x;
    #pragma unroll
    for (int it = 0; it < 16; ++it) {
        int e = tid + it * 256;
        int k = e >> 6, c = e & 63;
        ts[k][c] = W[(size_t)(k0 + k) * nc + c0 + c];
    }
    __syncthreads();
    #pragma unroll
    for (int it = 0; it < 16; ++it) {
        int e = tid + it * 256;
        int c = e >> 6, k = e & 63;
        WT[(size_t)(c0 + c) * 512 + k0 + k] = f2tf32(ts[k][c]);
    }
}

// ---------------------------------------------------------------------------
// TF32 tensor-core GEMM with fused LayerNorm on A.
//   out[b, rowBase+i, colBase+j] = (sum_k LN(src) * W + bias) * outScale
// Block tile 128x128, 256 threads (8 warps, 2x4, warp tile 64x32),
// mma.m16n8k8 tf32, KC=32 k-chunks. Smem stride 36 -> conflict-free frag LDS
// and STS.128 staging. indices: skip masked 128-row tiles (256-aligned mask).
// ---------------------------------------------------------------------------
__global__ void __launch_bounds__(256, 2)
gemm_tf32(const float* __restrict__ src, const float2* __restrict__ stats,
          const float* __restrict__ gln, const float* __restrict__ bln,
          const uint32_t* __restrict__ WT, const float* __restrict__ bias,
          float outScale, float* __restrict__ out, int nc, int T,
          const int* __restrict__ indices)
{
    const int b = blockIdx.z;
    const int rowBase = blockIdx.y * 128;
    const int colBase = blockIdx.x * 128;
    if (indices && rowBase >= indices[b] * 256) return;

    const float*  srcB  = src + ((size_t)b * T + rowBase) * DIMC;
    float*        outB  = out + ((size_t)b * T + rowBase) * (size_t)nc;
    const bool    ln    = (stats != nullptr);
    const float2* statB = ln ? (stats + (size_t)b * T + rowBase) : nullptr;

    __shared__ uint32_t As[128 * 36];
    __shared__ uint32_t Bs[128 * 36];
    __shared__ float    gs[512], bs[512];
    __shared__ float2   st[128];

    const int tid = threadIdx.x;
    if (ln) {
        #pragma unroll
        for (int u = 0; u < 2; ++u) {
            int k = tid + u * 256;
            gs[k] = gln[k];
            bs[k] = bln[k];
        }
        if (tid < 128) st[tid] = statB[tid];
    }
    __syncthreads();

    const int warp = tid >> 5, lane = tid & 31;
    const int wm = warp >> 2, wn = warp & 3;
    const int qr = lane >> 2, qc = lane & 3;

    float acc[4][4][4];
    #pragma unroll
    for (int i = 0; i < 4; ++i)
        #pragma unroll
        for (int j = 0; j < 4; ++j)
            #pragma unroll
            for (int r = 0; r < 4; ++r) acc[i][j][r] = 0.f;

    for (int k0 = 0; k0 < 512; k0 += 32) {
        // ---- stage A (LN + tf32 convert), row-major stride 36 ----
        #pragma unroll
        for (int u = 0; u < 4; ++u) {
            int e = tid + u * 256;
            int m = e >> 3, kq = (e & 7) * 4;
            float4 v = *(const float4*)(srcB + (size_t)m * DIMC + k0 + kq);
            if (ln) {
                float2 s = st[m];
                v.x = fmaf((v.x - s.x) * s.y, gs[k0 + kq + 0], bs[k0 + kq + 0]);
                v.y = fmaf((v.y - s.x) * s.y, gs[k0 + kq + 1], bs[k0 + kq + 1]);
                v.z = fmaf((v.z - s.x) * s.y, gs[k0 + kq + 2], bs[k0 + kq + 2]);
                v.w = fmaf((v.w - s.x) * s.y, gs[k0 + kq + 3], bs[k0 + kq + 3]);
            }
            uint4 t;
            t.x = f2tf32(v.x); t.y = f2tf32(v.y);
            t.z = f2tf32(v.z); t.w = f2tf32(v.w);
            *(uint4*)&As[m * 36 + kq] = t;
        }
        // ---- stage B (already tf32, k-contiguous), stride 36 ----
        #pragma unroll
        for (int u = 0; u < 4; ++u) {
            int e = tid + u * 256;
            int c = e >> 3, kq = (e & 7) * 4;
            *(uint4*)&Bs[c * 36 + kq] =
                *(const uint4*)(WT + (size_t)(colBase + c) * 512 + k0 + kq);
        }
        __syncthreads();

        // ---- 4 k-steps of m16n8k8 ----
        #pragma unroll
        for (int ks = 0; ks < 4; ++ks) {
            uint32_t a[4][4], bb[4][2];
            #pragma unroll
            for (int i = 0; i < 4; ++i) {
                int r0 = wm * 64 + i * 16 + qr;
                a[i][0] = As[(r0    ) * 36 + ks * 8 + qc    ];
                a[i][1] = As[(r0 + 8) * 36 + ks * 8 + qc    ];
                a[i][2] = As[(r0    ) * 36 + ks * 8 + qc + 4];
                a[i][3] = As[(r0 + 8) * 36 + ks * 8 + qc + 4];
            }
            #pragma unroll
            for (int j = 0; j < 4; ++j) {
                int c0 = wn * 32 + j * 8 + qr;
                bb[j][0] = Bs[c0 * 36 + ks * 8 + qc    ];
                bb[j][1] = Bs[c0 * 36 + ks * 8 + qc + 4];
            }
            #pragma unroll
            for (int i = 0; i < 4; ++i)
                #pragma unroll
                for (int j = 0; j < 4; ++j)
                    mma_tf32(acc[i][j], a[i], bb[j]);
        }
        __syncthreads();
    }

    // ---- epilogue: bias + scale ----
    #pragma unroll
    for (int i = 0; i < 4; ++i) {
        int r0 = wm * 64 + i * 16 + qr;
        #pragma unroll
        for (int j = 0; j < 4; ++j) {
            int col = colBase + wn * 32 + j * 8 + qc * 2;
            float2 bi = *(const float2*)(bias + col);
            float2 o0, o1;
            o0.x = (acc[i][j][0] + bi.x) * outScale;
            o0.y = (acc[i][j][1] + bi.y) * outScale;
            o1.x = (acc[i][j][2] + bi.x) * outScale;
            o1.y = (acc[i][j][3] + bi.y) * outScale;
            *(float2*)(outB + (size_t)(r0    ) * nc + col) = o0;
            *(float2*)(outB + (size_t)(r0 + 8) * nc + col) = o1;
        }
    }
}

// ---------------------------------------------------------------------------
// Split-KV flash attention (unchanged from R1).
// ---------------------------------------------------------------------------
__global__ void __launch_bounds__(256)
attn_split(const float* __restrict__ q, const int* __restrict__ indices)
{
    const int b = blockIdx.z, h = blockIdx.y, s = blockIdx.x;
    const int vis = indices[b];
    const bool is_lat = (s == 32);
    if (!is_lat && s >= vis) return;

    extern __shared__ float smdyn[];
    float* qs  = smdyn;
    float* Kt  = qs  + 64 * 64;
    float* Vs  = Kt  + 64 * 65;
    float* Ss  = Vs  + 64 * 65;
    float* m_s = Ss  + 64 * 65;
    float* l_s = m_s + 64;
    float* c_s = l_s + 64;

    const int tid = threadIdx.x;

    #pragma unroll
    for (int it = 0; it < 16; ++it) {
        int e = tid + it * 256;
        int r = e >> 6, c = e & 63;
        qs[r * 64 + c] = q[((size_t)b * SLAT + r) * INNERC + h * DHEAD + c];
    }
    if (tid < 64) { m_s[tid] = -CUDART_INF_F; l_s[tid] = 0.f; }

    const float* kvbase = is_lat
        ? (g_kvlat + (size_t)b * SLAT * 1024)
        : (g_kvmed + ((size_t)b * NMEDIA + (size_t)s * 256) * 1024);
    const int nch = is_lat ? 1 : 4;

    const int tx = tid & 15, ty = tid >> 4;
    float o[4][4] = {};

    for (int ch = 0; ch < nch; ++ch) {
        __syncthreads();
        #pragma unroll
        for (int it = 0; it < 16; ++it) {
            int e = tid + it * 256;
            int j = e >> 6, d = e & 63;
            const float* rp = kvbase + (size_t)(ch * 64 + j) * 1024 + h * DHEAD;
            Kt[d * 65 + j] = rp[d];
            Vs[j * 65 + d] = rp[512 + d];
        }
        __syncthreads();

        float sacc[4][4] = {};
        #pragma unroll 8
        for (int d = 0; d < 64; ++d) {
            float a0 = qs[(ty * 4 + 0) * 64 + d];
            float a1 = qs[(ty * 4 + 1) * 64 + d];
            float a2 = qs[(ty * 4 + 2) * 64 + d];
            float a3 = qs[(ty * 4 + 3) * 64 + d];
            float b0 = Kt[d * 65 + tx * 4 + 0];
            float b1 = Kt[d * 65 + tx * 4 + 1];
            float b2 = Kt[d * 65 + tx * 4 + 2];
            float b3 = Kt[d * 65 + tx * 4 + 3];
            sacc[0][0] = fmaf(a0, b0, sacc[0][0]); sacc[0][1] = fmaf(a0, b1, sacc[0][1]);
            sacc[0][2] = fmaf(a0, b2, sacc[0][2]); sacc[0][3] = fmaf(a0, b3, sacc[0][3]);
            sacc[1][0] = fmaf(a1, b0, sacc[1][0]); sacc[1][1] = fmaf(a1, b1, sacc[1][1]);
            sacc[1][2] = fmaf(a1, b2, sacc[1][2]); sacc[1][3] = fmaf(a1, b3, sacc[1][3]);
            sacc[2][0] = fmaf(a2, b0, sacc[2][0]); sacc[2][1] = fmaf(a2, b1, sacc[2][1]);
            sacc[2][2] = fmaf(a2, b2, sacc[2][2]); sacc[2][3] = fmaf(a2, b3, sacc[2][3]);
            sacc[3][0] = fmaf(a3, b0, sacc[3][0]); sacc[3][1] = fmaf(a3, b1, sacc[3][1]);
            sacc[3][2] = fmaf(a3, b2, sacc[3][2]); sacc[3][3] = fmaf(a3, b3, sacc[3][3]);
        }
        #pragma unroll
        for (int r = 0; r < 4; ++r)
            #pragma unroll
            for (int c = 0; c < 4; ++c)
                Ss[(ty * 4 + r) * 65 + tx * 4 + c] = sacc[r][c];
        __syncthreads();

        if (tid < 64) {
            const int i = tid;
            float rm = -CUDART_INF_F;
            #pragma unroll 8
            for (int j = 0; j < 64; ++j) rm = fmaxf(rm, Ss[i * 65 + j]);
            float mo = m_s[i];
            float mn = fmaxf(mo, rm);
            float cc = __expf(mo - mn);
            float sum = 0.f;
            #pragma unroll 8
            for (int j = 0; j < 64; ++j) {
                float p = __expf(Ss[i * 65 + j] - mn);
                Ss[i * 65 + j] = p;
                sum += p;
            }
            m_s[i] = mn;
            l_s[i] = fmaf(l_s[i], cc, sum);
            c_s[i] = cc;
        }
        __syncthreads();

        float c0 = c_s[ty * 4 + 0], c1 = c_s[ty * 4 + 1];
        float c2 = c_s[ty * 4 + 2], c3 = c_s[ty * 4 + 3];
        #pragma unroll
        for (int c = 0; c < 4; ++c) {
            o[0][c] *= c0; o[1][c] *= c1; o[2][c] *= c2; o[3][c] *= c3;
        }
        #pragma unroll 8
        for (int j = 0; j < 64; ++j) {
            float p0 = Ss[(ty * 4 + 0) * 65 + j];
            float p1 = Ss[(ty * 4 + 1) * 65 + j];
            float p2 = Ss[(ty * 4 + 2) * 65 + j];
            float p3 = Ss[(ty * 4 + 3) * 65 + j];
            float v0 = Vs[j * 65 + tx * 4 + 0];
            float v1 = Vs[j * 65 + tx * 4 + 1];
            float v2 = Vs[j * 65 + tx * 4 + 2];
            float v3 = Vs[j * 65 + tx * 4 + 3];
            o[0][0] = fmaf(p0, v0, o[0][0]); o[0][1] = fmaf(p0, v1, o[0][1]);
            o[0][2] = fmaf(p0, v2, o[0][2]); o[0][3] = fmaf(p0, v3, o[0][3]);
            o[1][0] = fmaf(p1, v0, o[1][0]); o[1][1] = fmaf(p1, v1, o[1][1]);
            o[1][2] = fmaf(p1, v2, o[1][2]); o[1][3] = fmaf(p1, v3, o[1][3]);
            o[2][0] = fmaf(p2, v0, o[2][0]); o[2][1] = fmaf(p2, v1, o[2][1]);
            o[2][2] = fmaf(p2, v2, o[2][2]); o[2][3] = fmaf(p2, v3, o[2][3]);
            o[3][0] = fmaf(p3, v0, o[3][0]); o[3][1] = fmaf(p3, v1, o[3][1]);
            o[3][2] = fmaf(p3, v2, o[3][2]); o[3][3] = fmaf(p3, v3, o[3][3]);
        }
    }

    const size_t pbase = ((size_t)(b * HEADS + h)) * NSPLIT + s;
    float* op = g_opart + pbase * (SLAT * DHEAD);
    #pragma unroll
    for (int r = 0; r < 4; ++r)
        #pragma unroll
        for (int c = 0; c < 4; ++c)
            op[(ty * 4 + r) * DHEAD + tx * 4 + c] = o[r][c];
    if (tid < 64) {
        g_mpart[pbase * SLAT + tid] = m_s[tid];
        g_lpart[pbase * SLAT + tid] = l_s[tid];
    }
}

// ---------------------------------------------------------------------------
// Combine split partials -> attn_out. grid (64 bh, 8 row-groups), one warp per
// query row; lane = split for the weight pass, lane = 2 dims for accumulate.
// ---------------------------------------------------------------------------
__global__ void __launch_bounds__(256)
attn_combine(const int* __restrict__ indices, float* __restrict__ attn_out)
{
    const int bh = blockIdx.x;
    const int b = bh >> 3, h = bh & 7;
    const int vis = indices[b];
    const int warp = threadIdx.x >> 5, lane = threadIdx.x & 31;
    const int i = blockIdx.y * 8 + warp;

    __shared__ float ws[8][33];
    __shared__ float linv[8];

    const size_t base = (size_t)bh * NSPLIT;

    float m    = (lane < vis) ? g_mpart[(base + lane) * SLAT + i] : -CUDART_INF_F;
    float mlat = g_mpart[(base + 32) * SLAT + i];
    float mm = fmaxf(m, mlat);
    #pragma unroll
    for (int o = 16; o > 0; o >>= 1)
        mm = fmaxf(mm, __shfl_xor_sync(0xffffffffu, mm, o));

    float w  = (lane < vis) ? __expf(m - mm) : 0.f;
    float wl = __expf(mlat - mm);
    float l  = (lane < vis) ? g_lpart[(base + lane) * SLAT + i] * w : 0.f;
    #pragma unroll
    for (int o = 16; o > 0; o >>= 1)
        l += __shfl_xor_sync(0xffffffffu, l, o);
    float ll = g_lpart[(base + 32) * SLAT + i] * wl;

    ws[warp][lane] = w;
    if (lane == 0) {
        ws[warp][32] = wl;
        linv[warp] = 1.f / (l + ll);
    }
    __syncwarp();

    const int d = lane * 2;
    float2 v = *(const float2*)(g_opart + (base + 32) * 4096 + i * 64 + d);
    float a0 = v.x * ws[warp][32];
    float a1 = v.y * ws[warp][32];
    for (int s = 0; s < vis; ++s) {
        float wv = ws[warp][s];
        float2 u = *(const float2*)(g_opart + (base + s) * 4096 + i * 64 + d);
        a0 = fmaf(u.x, wv, a0);
        a1 = fmaf(u.y, wv, a1);
    }
    float li = linv[warp];
    float2 r = make_float2(a0 * li, a1 * li);
    *(float2*)(attn_out + ((size_t)b * SLAT + i) * INNERC + h * DHEAD + d) = r;
}

// ---------------------------------------------------------------------------
// Launch
// ---------------------------------------------------------------------------
#define ATTN_SMEM ((64 * 64 + 3 * 64 * 65 + 3 * 64) * (int)sizeof(float))

extern "C" void kernel_launch(void* const* d_in, const int* in_sizes, int n_in,
                              void* d_out, int out_size)
{
    (void)in_sizes; (void)n_in; (void)out_size;
    const float* x    = (const float*)d_in[0];
    const float* lat  = (const float*)d_in[1];
    const int*   idx  = (const int*)  d_in[2];
    const float* g_m  = (const float*)d_in[3];
    const float* b_m  = (const float*)d_in[4];
    const float* g_l  = (const float*)d_in[5];
    const float* b_l  = (const float*)d_in[6];
    const float* Wq   = (const float*)d_in[7];
    const float* bq   = (const float*)d_in[8];
    const float* Wkv  = (const float*)d_in[9];
    const float* bkv  = (const float*)d_in[10];
    const float* Wo   = (const float*)d_in[11];
    const float* bo   = (const float*)d_in[12];
    float* out = (float*)d_out;

    void *pq, *pkvlat, *pkvmed, *pattno, *psm, *psl, *pwq, *pwkv, *pwo;
    cudaGetSymbolAddress(&pq,     g_q);
    cudaGetSymbolAddress(&pkvlat, g_kvlat);
    cudaGetSymbolAddress(&pkvmed, g_kvmed);
    cudaGetSymbolAddress(&pattno, g_attno);
    cudaGetSymbolAddress(&psm,    g_stat_med);
    cudaGetSymbolAddress(&psl,    g_stat_lat);
    cudaGetSymbolAddress(&pwq,    g_WqT);
    cudaGetSymbolAddress(&pwkv,   g_WkvT);
    cudaGetSymbolAddress(&pwo,    g_WoT);

    cudaFuncSetAttribute(attn_split,
                         cudaFuncAttributeMaxDynamicSharedMemorySize, ATTN_SMEM);

    // LN statistics (media with mask skip; latents flattened to 512 rows)
    ln_stats<<<BATCH * NMEDIA / 8, 256>>>(x,   (float2*)psm, idx, NMEDIA);
    ln_stats<<<BATCH * SLAT   / 8, 256>>>(lat, (float2*)psl, nullptr, 0);

    // Weight transpose + tf32 convert
    transpose_w<<<dim3(16, 8, 3), 256>>>(Wq, Wkv, Wo,
                                         (uint32_t*)pwq, (uint32_t*)pwkv,
                                         (uint32_t*)pwo);

    // q = (LN(latents) @ Wq + bq) * SCALE   (batches flattened: 512 rows)
    gemm_tf32<<<dim3(4, 4, 1), 256>>>(lat, (const float2*)psl, g_l, b_l,
                                      (const uint32_t*)pwq, bq, 0.125f,
                                      (float*)pq, 512, 512, nullptr);
    // [k|v] latents
    gemm_tf32<<<dim3(8, 4, 1), 256>>>(lat, (const float2*)psl, g_l, b_l,
                                      (const uint32_t*)pwkv, bkv, 1.0f,
                                      (float*)pkvlat, 1024, 512, nullptr);
    // [k|v] visible media tokens (mask-skipped at 128-row tile level)
    gemm_tf32<<<dim3(8, 64, 8), 256>>>(x, (const float2*)psm, g_m, b_m,
                                       (const uint32_t*)pwkv, bkv, 1.0f,
                                       (float*)pkvmed, 1024, NMEDIA, idx);

    // attention
    attn_split<<<dim3(NSPLIT, HEADS, BATCH), 256, ATTN_SMEM>>>((const float*)pq, idx);
    attn_combine<<<dim3(64, 8), 256>>>(idx, (float*)pattno);

    // output projection (no LN)
    gemm_tf32<<<dim3(4, 4, 1), 256>>>((const float*)pattno, nullptr, nullptr, nullptr,
                                      (const uint32_t*)pwo, bo, 1.0f,
                                      out, 512, 512, nullptr);
}

// round 3
// speedup vs baseline: 3.6329x; 1.3726x over previous
#include <cuda_runtime.h>
#include <math_constants.h>
#include <cstdint>
#include <cstddef>

// ---------------------------------------------------------------------------
// Problem constants
// ---------------------------------------------------------------------------
#define BATCH   8
#define NMEDIA  8192
#define SLAT    64
#define DIMC    512
#define HEADS   8
#define DHEAD   64
#define INNERC  512
#define NSPLIT  33

// ---------------------------------------------------------------------------
// Scratch (device globals)
// ---------------------------------------------------------------------------
__device__ float    g_latproj[(size_t)BATCH * SLAT * 1536];        // [q | k | v]
__device__ float    g_kvmed [(size_t)BATCH * NMEDIA * 2 * INNERC];
__device__ float    g_opart [(size_t)BATCH * HEADS * NSPLIT * SLAT * DHEAD];
__device__ float    g_mpart [(size_t)BATCH * HEADS * NSPLIT * SLAT];
__device__ float    g_lpart [(size_t)BATCH * HEADS * NSPLIT * SLAT];
__device__ float    g_attno [(size_t)BATCH * SLAT * INNERC];
__device__ float2   g_stat_med[(size_t)BATCH * NMEDIA];
__device__ float2   g_stat_lat[(size_t)BATCH * SLAT];
__device__ uint32_t g_Wcat[(size_t)1536 * DIMC];   // [Wq*0.125 | Wkv] transposed, tf32
__device__ uint32_t g_WoT [(size_t)DIMC * INNERC];
__device__ float    g_bcat[1536];

// ---------------------------------------------------------------------------
// Helpers
// ---------------------------------------------------------------------------
__device__ __forceinline__ uint32_t f2tf32(float x) {
    uint32_t r;
    asm("cvt.rna.tf32.f32 %0, %1;" : "=r"(r) : "f"(x));
    return r;
}

__device__ __forceinline__ void mma_tf32(float* c, const uint32_t* a, const uint32_t* b) {
    asm volatile(
        "mma.sync.aligned.m16n8k8.row.col.f32.tf32.tf32.f32 "
        "{%0,%1,%2,%3},{%4,%5,%6,%7},{%8,%9},{%0,%1,%2,%3};"
        : "+f"(c[0]), "+f"(c[1]), "+f"(c[2]), "+f"(c[3])
        : "r"(a[0]), "r"(a[1]), "r"(a[2]), "r"(a[3]), "r"(b[0]), "r"(b[1]));
}

__device__ __forceinline__ void cp16(void* smem, const void* gmem) {
    uint32_t a = (uint32_t)__cvta_generic_to_shared(smem);
    asm volatile("cp.async.cg.shared.global [%0], [%1], 16;" :: "r"(a), "l"(gmem));
}
#define CP_COMMIT() asm volatile("cp.async.commit_group;")
#define CP_WAIT0()  asm volatile("cp.async.wait_group 0;")

// ---------------------------------------------------------------------------
// LayerNorm statistics: one warp per row.
// ---------------------------------------------------------------------------
__global__ void __launch_bounds__(256)
ln_stats(const float* __restrict__ src, float2* __restrict__ stats,
         const int* __restrict__ indices, int rowsPerBatch)
{
    const int row0 = blockIdx.x * 8;
    if (indices) {
        const int b  = row0 / rowsPerBatch;
        const int lr = row0 % rowsPerBatch;
        if (lr >= indices[b] * 256) return;
    }
    const int warp = threadIdx.x >> 5, lane = threadIdx.x & 31;
    const int row = row0 + warp;
    const float* r = src + (size_t)row * DIMC;
    float s = 0.f, q2 = 0.f;
    #pragma unroll
    for (int u = 0; u < 4; ++u) {
        float4 v = *(const float4*)(r + u * 128 + lane * 4);
        s += v.x + v.y + v.z + v.w;
        q2 = fmaf(v.x, v.x, q2); q2 = fmaf(v.y, v.y, q2);
        q2 = fmaf(v.z, v.z, q2); q2 = fmaf(v.w, v.w, q2);
    }
    #pragma unroll
    for (int o = 16; o > 0; o >>= 1) {
        s  += __shfl_xor_sync(0xffffffffu, s,  o);
        q2 += __shfl_xor_sync(0xffffffffu, q2, o);
    }
    if (lane == 0) {
        float mu  = s * (1.f / 512.f);
        float var = fmaf(-mu, mu, q2 * (1.f / 512.f));
        stats[row] = make_float2(mu, rsqrtf(var + 1e-5f));
    }
}

// ---------------------------------------------------------------------------
// Weight transpose + tf32 convert + scale folding + bias concat.
//   z=0: Wq*0.125 -> g_Wcat[0:512],  z=1: Wkv -> g_Wcat[512:1536], z=2: Wo -> g_WoT
// ---------------------------------------------------------------------------
__global__ void __launch_bounds__(256)
transpose_w(const float* __restrict__ Wq, const float* __restrict__ Wkv,
            const float* __restrict__ Wo, const float* __restrict__ bq,
            const float* __restrict__ bkv,
            uint32_t* __restrict__ Wcat, uint32_t* __restrict__ WoT,
            float* __restrict__ bcat)
{
    const float* W; uint32_t* WT; int nc; float scale = 1.f;
    if      (blockIdx.z == 0) { W = Wq;  WT = Wcat;             nc = 512;  scale = 0.125f; }
    else if (blockIdx.z == 1) { W = Wkv; WT = Wcat + 512 * 512; nc = 1024; }
    else                      { W = Wo;  WT = WoT;              nc = 512;  }
    const int c0 = blockIdx.x * 64;
    if (c0 >= nc) return;
    const int k0 = blockIdx.y * 64;
    const int tid = threadIdx.x;

    if (blockIdx.z == 0 && blockIdx.x == 0 && blockIdx.y == 0) {
        for (int i = tid; i < 512;  i += 256) bcat[i] = bq[i] * 0.125f;
        for (int i = tid; i < 1024; i += 256) bcat[512 + i] = bkv[i];
    }

    __shared__ float ts[64][65];
    #pragma unroll
    for (int it = 0; it < 16; ++it) {
        int e = tid + it * 256;
        int k = e >> 6, c = e & 63;
        ts[k][c] = W[(size_t)(k0 + k) * nc + c0 + c] * scale;
    }
    __syncthreads();
    #pragma unroll
    for (int it = 0; it < 16; ++it) {
        int e = tid + it * 256;
        int c = e >> 6, k = e & 63;
        WT[(size_t)(c0 + c) * 512 + k0 + k] = f2tf32(ts[k][c]);
    }
}

// ---------------------------------------------------------------------------
// Pipelined TF32 GEMM with fused LayerNorm on A.
// 128x128 tile, 256 threads, KC=32, double-buffered smem:
//   B via cp.async, A via register prefetch (LDG early, LN+cvt+STS after MMA).
// ---------------------------------------------------------------------------
__global__ void __launch_bounds__(256, 2)
gemm_tf32(const float* __restrict__ src, const float2* __restrict__ stats,
          const float* __restrict__ gln, const float* __restrict__ bln,
          const uint32_t* __restrict__ WT, const float* __restrict__ bias,
          float* __restrict__ out, int nc, int T,
          const int* __restrict__ indices)
{
    const int b = blockIdx.z;
    const int rowBase = blockIdx.y * 128;
    const int colBase = blockIdx.x * 128;
    if (indices && rowBase >= indices[b] * 256) return;

    const float*  srcB  = src + ((size_t)b * T + rowBase) * DIMC;
    float*        outB  = out + ((size_t)b * T + rowBase) * (size_t)nc;
    const bool    ln    = (stats != nullptr);
    const float2* statB = ln ? (stats + (size_t)b * T + rowBase) : nullptr;

    extern __shared__ uint32_t dynsm[];
    uint32_t* As = dynsm;                 // [2][128*36]
    uint32_t* Bs = dynsm + 2 * 128 * 36;  // [2][128*36]
    __shared__ float  gs[512], bs[512];
    __shared__ float2 st[128];

    const int tid = threadIdx.x;
    if (ln) {
        #pragma unroll
        for (int u = 0; u < 2; ++u) {
            int k = tid + u * 256;
            gs[k] = gln[k];
            bs[k] = bln[k];
        }
        if (tid < 128) st[tid] = statB[tid];
        __syncthreads();
    }

    const int am = tid >> 3, akq = (tid & 7) * 4;   // A staging coords (per 256-slot pass)
    float4 rv[4];

    // --- A load (k-chunk k0) into registers ---
    auto lda = [&](int k0) {
        #pragma unroll
        for (int u = 0; u < 4; ++u) {
            int m = am + u * 32;
            rv[u] = *(const float4*)(srcB + (size_t)m * DIMC + k0 + akq);
        }
    };
    // --- transform + store A registers into buffer ---
    auto sta = [&](int k0, int buf) {
        #pragma unroll
        for (int u = 0; u < 4; ++u) {
            int m = am + u * 32;
            float4 v = rv[u];
            if (ln) {
                float2 s = st[m];
                v.x = fmaf((v.x - s.x) * s.y, gs[k0 + akq + 0], bs[k0 + akq + 0]);
                v.y = fmaf((v.y - s.x) * s.y, gs[k0 + akq + 1], bs[k0 + akq + 1]);
                v.z = fmaf((v.z - s.x) * s.y, gs[k0 + akq + 2], bs[k0 + akq + 2]);
                v.w = fmaf((v.w - s.x) * s.y, gs[k0 + akq + 3], bs[k0 + akq + 3]);
            }
            uint4 t;
            t.x = f2tf32(v.x); t.y = f2tf32(v.y);
            t.z = f2tf32(v.z); t.w = f2tf32(v.w);
            *(uint4*)&As[buf * 4608 + m * 36 + akq] = t;
        }
    };
    // --- B cp.async (k-chunk k0) into buffer ---
    auto cpb = [&](int k0, int buf) {
        #pragma unroll
        for (int u = 0; u < 4; ++u) {
            int c = am + u * 32;
            cp16(&Bs[buf * 4608 + c * 36 + akq],
                 WT + (size_t)(colBase + c) * 512 + k0 + akq);
        }
        CP_COMMIT();
    };

    const int warp = tid >> 5, lane = tid & 31;
    const int wm = warp >> 2, wn = warp & 3;
    const int qr = lane >> 2, qc = lane & 3;

    float acc[4][4][4];
    #pragma unroll
    for (int i = 0; i < 4; ++i)
        #pragma unroll
        for (int j = 0; j < 4; ++j)
            #pragma unroll
            for (int r = 0; r < 4; ++r) acc[i][j][r] = 0.f;

    lda(0); sta(0, 0); cpb(0, 0);

    for (int kc = 0; kc < 16; ++kc) {
        const int buf = kc & 1;
        CP_WAIT0();
        __syncthreads();

        const bool nxt = (kc < 15);
        if (nxt) { lda((kc + 1) * 32); cpb((kc + 1) * 32, buf ^ 1); }

        const uint32_t* Ab = As + buf * 4608;
        const uint32_t* Bb = Bs + buf * 4608;
        #pragma unroll
        for (int ks = 0; ks < 4; ++ks) {
            uint32_t a[4][4], bb[4][2];
            #pragma unroll
            for (int i = 0; i < 4; ++i) {
                int r0 = wm * 64 + i * 16 + qr;
                a[i][0] = Ab[(r0    ) * 36 + ks * 8 + qc    ];
                a[i][1] = Ab[(r0 + 8) * 36 + ks * 8 + qc    ];
                a[i][2] = Ab[(r0    ) * 36 + ks * 8 + qc + 4];
                a[i][3] = Ab[(r0 + 8) * 36 + ks * 8 + qc + 4];
            }
            #pragma unroll
            for (int j = 0; j < 4; ++j) {
                int c0 = wn * 32 + j * 8 + qr;
                bb[j][0] = Bb[c0 * 36 + ks * 8 + qc    ];
                bb[j][1] = Bb[c0 * 36 + ks * 8 + qc + 4];
            }
            #pragma unroll
            for (int i = 0; i < 4; ++i)
                #pragma unroll
                for (int j = 0; j < 4; ++j)
                    mma_tf32(acc[i][j], a[i], bb[j]);
        }

        if (nxt) sta((kc + 1) * 32, buf ^ 1);
    }

    #pragma unroll
    for (int i = 0; i < 4; ++i) {
        int r0 = wm * 64 + i * 16 + qr;
        #pragma unroll
        for (int j = 0; j < 4; ++j) {
            int col = colBase + wn * 32 + j * 8 + qc * 2;
            float2 bi = *(const float2*)(bias + col);
            float2 o0, o1;
            o0.x = acc[i][j][0] + bi.x;
            o0.y = acc[i][j][1] + bi.y;
            o1.x = acc[i][j][2] + bi.x;
            o1.y = acc[i][j][3] + bi.y;
            *(float2*)(outB + (size_t)(r0    ) * nc + col) = o0;
            *(float2*)(outB + (size_t)(r0 + 8) * nc + col) = o1;
        }
    }
}
#define GEMM_SMEM (4 * 128 * 36 * (int)sizeof(uint32_t))

// ---------------------------------------------------------------------------
// Tensor-core split-KV flash attention. 128 threads = 4 warps, warp = 16 rows.
// S and O accumulators in registers; softmax via quad shuffles; P through
// per-warp smem. Strides: A-operands 68, B-operands 72 (conflict-free frags).
// ---------------------------------------------------------------------------
__global__ void __launch_bounds__(128)
attn_split_tc(const float* __restrict__ latproj, const int* __restrict__ indices)
{
    const int b = blockIdx.z, h = blockIdx.y, s = blockIdx.x;
    const int vis = indices[b];
    const bool is_lat = (s == 32);
    if (!is_lat && s >= vis) return;

    extern __shared__ float smf[];
    float*    Ks = smf;                              // [64][72]
    float*    Vs = Ks + 64 * 72;                     // [64][72]
    uint32_t* Qs = (uint32_t*)(Vs + 64 * 72);        // [64][68] tf32
    uint32_t* Ps = Qs + 64 * 68;                     // [64][68] tf32 (per-warp rows)

    const int tid = threadIdx.x, warp = tid >> 5, lane = tid & 31;
    const int qr = lane >> 2, qc = lane & 3;
    const int r0 = warp * 16 + qr;

    // load Q (rna tf32): q is cols [0,512) of latproj
    #pragma unroll
    for (int it = 0; it < 8; ++it) {
        int e = tid + it * 128;
        int r = e >> 4, cq = (e & 15) * 4;
        float4 v = *(const float4*)(latproj + ((size_t)b * 64 + r) * 1536 + h * 64 + cq);
        uint4 t;
        t.x = f2tf32(v.x); t.y = f2tf32(v.y);
        t.z = f2tf32(v.z); t.w = f2tf32(v.w);
        *(uint4*)&Qs[r * 68 + cq] = t;
    }

    const float* kvbase; int ldkv, koff, voff, nch;
    if (is_lat) {
        kvbase = latproj + (size_t)b * 64 * 1536;
        ldkv = 1536; koff = 512 + h * 64; voff = 1024 + h * 64; nch = 1;
    } else {
        kvbase = g_kvmed + ((size_t)b * NMEDIA + (size_t)s * 256) * 1024;
        ldkv = 1024; koff = h * 64; voff = 512 + h * 64; nch = 4;
    }

    float m0 = -CUDART_INF_F, m1 = -CUDART_INF_F, l0 = 0.f, l1 = 0.f;
    float o[8][4];
    #pragma unroll
    for (int nf = 0; nf < 8; ++nf)
        #pragma unroll
        for (int r = 0; r < 4; ++r) o[nf][r] = 0.f;

    for (int ch = 0; ch < nch; ++ch) {
        __syncthreads();
        // stage K, V (rna tf32)
        #pragma unroll
        for (int it = 0; it < 8; ++it) {
            int e = tid + it * 128;
            int j = e >> 4, dq = (e & 15) * 4;
            const float* rp = kvbase + (size_t)(ch * 64 + j) * ldkv;
            float4 kv = *(const float4*)(rp + koff + dq);
            float4 vv = *(const float4*)(rp + voff + dq);
            uint32_t* kd = (uint32_t*)&Ks[j * 72 + dq];
            kd[0] = f2tf32(kv.x); kd[1] = f2tf32(kv.y);
            kd[2] = f2tf32(kv.z); kd[3] = f2tf32(kv.w);
            uint32_t* vd = (uint32_t*)&Vs[j * 72 + dq];
            vd[0] = f2tf32(vv.x); vd[1] = f2tf32(vv.y);
            vd[2] = f2tf32(vv.z); vd[3] = f2tf32(vv.w);
        }
        __syncthreads();

        // ---- S = Q @ K^T ----
        float sacc[8][4] = {};
        const uint32_t* Ku = (const uint32_t*)Ks;
        #pragma unroll
        for (int ks = 0; ks < 8; ++ks) {
            uint32_t a[4];
            a[0] = Qs[(r0    ) * 68 + ks * 8 + qc    ];
            a[1] = Qs[(r0 + 8) * 68 + ks * 8 + qc    ];
            a[2] = Qs[(r0    ) * 68 + ks * 8 + qc + 4];
            a[3] = Qs[(r0 + 8) * 68 + ks * 8 + qc + 4];
            #pragma unroll
            for (int nf = 0; nf < 8; ++nf) {
                uint32_t bb[2];
                bb[0] = Ku[(nf * 8 + qr) * 72 + ks * 8 + qc    ];
                bb[1] = Ku[(nf * 8 + qr) * 72 + ks * 8 + qc + 4];
                mma_tf32(sacc[nf], a, bb);
            }
        }

        // ---- online softmax (rows r0, r0+8; quad reduction) ----
        float rm0 = -CUDART_INF_F, rm1 = -CUDART_INF_F;
        #pragma unroll
        for (int nf = 0; nf < 8; ++nf) {
            rm0 = fmaxf(rm0, fmaxf(sacc[nf][0], sacc[nf][1]));
            rm1 = fmaxf(rm1, fmaxf(sacc[nf][2], sacc[nf][3]));
        }
        rm0 = fmaxf(rm0, __shfl_xor_sync(0xffffffffu, rm0, 1));
        rm0 = fmaxf(rm0, __shfl_xor_sync(0xffffffffu, rm0, 2));
        rm1 = fmaxf(rm1, __shfl_xor_sync(0xffffffffu, rm1, 1));
        rm1 = fmaxf(rm1, __shfl_xor_sync(0xffffffffu, rm1, 2));
        float mn0 = fmaxf(m0, rm0), mn1 = fmaxf(m1, rm1);
        float cc0 = __expf(m0 - mn0), cc1 = __expf(m1 - mn1);
        float s0 = 0.f, s1 = 0.f;
        #pragma unroll
        for (int nf = 0; nf < 8; ++nf) {
            float p00 = __expf(sacc[nf][0] - mn0);
            float p01 = __expf(sacc[nf][1] - mn0);
            float p10 = __expf(sacc[nf][2] - mn1);
            float p11 = __expf(sacc[nf][3] - mn1);
            s0 += p00 + p01; s1 += p10 + p11;
            *(uint2*)&Ps[(r0    ) * 68 + nf * 8 + qc * 2] =
                make_uint2(f2tf32(p00), f2tf32(p01));
            *(uint2*)&Ps[(r0 + 8) * 68 + nf * 8 + qc * 2] =
                make_uint2(f2tf32(p10), f2tf32(p11));
            o[nf][0] *= cc0; o[nf][1] *= cc0;
            o[nf][2] *= cc1; o[nf][3] *= cc1;
        }
        s0 += __shfl_xor_sync(0xffffffffu, s0, 1);
        s0 += __shfl_xor_sync(0xffffffffu, s0, 2);
        s1 += __shfl_xor_sync(0xffffffffu, s1, 1);
        s1 += __shfl_xor_sync(0xffffffffu, s1, 2);
        m0 = mn0; m1 = mn1;
        l0 = fmaf(l0, cc0, s0);
        l1 = fmaf(l1, cc1, s1);
        __syncwarp();

        // ---- O += P @ V ----
        const uint32_t* Vu = (const uint32_t*)Vs;
        #pragma unroll
        for (int ks = 0; ks < 8; ++ks) {
            uint32_t a[4];
            a[0] = Ps[(r0    ) * 68 + ks * 8 + qc    ];
            a[1] = Ps[(r0 + 8) * 68 + ks * 8 + qc    ];
            a[2] = Ps[(r0    ) * 68 + ks * 8 + qc + 4];
            a[3] = Ps[(r0 + 8) * 68 + ks * 8 + qc + 4];
            #pragma unroll
            for (int nf = 0; nf < 8; ++nf) {
                uint32_t bb[2];
                bb[0] = Vu[(ks * 8 + qc    ) * 72 + nf * 8 + qr];
                bb[1] = Vu[(ks * 8 + qc + 4) * 72 + nf * 8 + qr];
                mma_tf32(o[nf], a, bb);
            }
        }
    }

    // ---- write partials ----
    const size_t pbase = ((size_t)(b * HEADS + h)) * NSPLIT + s;
    float* op = g_opart + pbase * 4096;
    #pragma unroll
    for (int nf = 0; nf < 8; ++nf) {
        *(float2*)&op[(r0    ) * 64 + nf * 8 + qc * 2] = make_float2(o[nf][0], o[nf][1]);
        *(float2*)&op[(r0 + 8) * 64 + nf * 8 + qc * 2] = make_float2(o[nf][2], o[nf][3]);
    }
    if (qc == 0) {
        g_mpart[pbase * 64 + r0    ] = m0;
        g_mpart[pbase * 64 + r0 + 8] = m1;
        g_lpart[pbase * 64 + r0    ] = l0;
        g_lpart[pbase * 64 + r0 + 8] = l1;
    }
}
#define ATTN_SMEM ((2 * 64 * 72 + 2 * 64 * 68) * (int)sizeof(float))

// ---------------------------------------------------------------------------
// Combine split partials -> attn_out.
// ---------------------------------------------------------------------------
__global__ void __launch_bounds__(256)
attn_combine(const int* __restrict__ indices, float* __restrict__ attn_out)
{
    const int bh = blockIdx.x;
    const int b = bh >> 3, h = bh & 7;
    const int vis = indices[b];
    const int warp = threadIdx.x >> 5, lane = threadIdx.x & 31;
    const int i = blockIdx.y * 8 + warp;

    __shared__ float ws[8][33];
    __shared__ float linv[8];

    const size_t base = (size_t)bh * NSPLIT;

    float m    = (lane < vis) ? g_mpart[(base + lane) * SLAT + i] : -CUDART_INF_F;
    float mlat = g_mpart[(base + 32) * SLAT + i];
    float mm = fmaxf(m, mlat);
    #pragma unroll
    for (int o = 16; o > 0; o >>= 1)
        mm = fmaxf(mm, __shfl_xor_sync(0xffffffffu, mm, o));

    float w  = (lane < vis) ? __expf(m - mm) : 0.f;
    float wl = __expf(mlat - mm);
    float l  = (lane < vis) ? g_lpart[(base + lane) * SLAT + i] * w : 0.f;
    #pragma unroll
    for (int o = 16; o > 0; o >>= 1)
        l += __shfl_xor_sync(0xffffffffu, l, o);
    float ll = g_lpart[(base + 32) * SLAT + i] * wl;

    ws[warp][lane] = w;
    if (lane == 0) {
        ws[warp][32] = wl;
        linv[warp] = 1.f / (l + ll);
    }
    __syncwarp();

    const int d = lane * 2;
    float2 v = *(const float2*)(g_opart + (base + 32) * 4096 + i * 64 + d);
    float a0 = v.x * ws[warp][32];
    float a1 = v.y * ws[warp][32];
    for (int s = 0; s < vis; ++s) {
        float wv = ws[warp][s];
        float2 u = *(const float2*)(g_opart + (base + s) * 4096 + i * 64 + d);
        a0 = fmaf(u.x, wv, a0);
        a1 = fmaf(u.y, wv, a1);
    }
    float li = linv[warp];
    float2 r = make_float2(a0 * li, a1 * li);
    *(float2*)(attn_out + ((size_t)b * SLAT + i) * INNERC + h * DHEAD + d) = r;
}

// ---------------------------------------------------------------------------
// Launch
// ---------------------------------------------------------------------------
extern "C" void kernel_launch(void* const* d_in, const int* in_sizes, int n_in,
                              void* d_out, int out_size)
{
    (void)in_sizes; (void)n_in; (void)out_size;
    const float* x    = (const float*)d_in[0];
    const float* lat  = (const float*)d_in[1];
    const int*   idx  = (const int*)  d_in[2];
    const float* g_m  = (const float*)d_in[3];
    const float* b_m  = (const float*)d_in[4];
    const float* g_l  = (const float*)d_in[5];
    const float* b_l  = (const float*)d_in[6];
    const float* Wq   = (const float*)d_in[7];
    const float* bq   = (const float*)d_in[8];
    const float* Wkv  = (const float*)d_in[9];
    const float* bkv  = (const float*)d_in[10];
    const float* Wo   = (const float*)d_in[11];
    const float* bo   = (const float*)d_in[12];
    float* out = (float*)d_out;

    void *plp, *pkvmed, *pattno, *psm, *psl, *pwcat, *pwo, *pbcat;
    cudaGetSymbolAddress(&plp,    g_latproj);
    cudaGetSymbolAddress(&pkvmed, g_kvmed);
    cudaGetSymbolAddress(&pattno, g_attno);
    cudaGetSymbolAddress(&psm,    g_stat_med);
    cudaGetSymbolAddress(&psl,    g_stat_lat);
    cudaGetSymbolAddress(&pwcat,  g_Wcat);
    cudaGetSymbolAddress(&pwo,    g_WoT);
    cudaGetSymbolAddress(&pbcat,  g_bcat);

    cudaFuncSetAttribute(gemm_tf32,
                         cudaFuncAttributeMaxDynamicSharedMemorySize, GEMM_SMEM);
    cudaFuncSetAttribute(attn_split_tc,
                         cudaFuncAttributeMaxDynamicSharedMemorySize, ATTN_SMEM);

    // LN statistics
    ln_stats<<<BATCH * NMEDIA / 8, 256>>>(x,   (float2*)psm, idx, NMEDIA);
    ln_stats<<<BATCH * SLAT   / 8, 256>>>(lat, (float2*)psl, nullptr, 0);

    // Weight prep
    transpose_w<<<dim3(16, 8, 3), 256>>>(Wq, Wkv, Wo, bq, bkv,
                                         (uint32_t*)pwcat, (uint32_t*)pwo,
                                         (float*)pbcat);

    // latent projections: [q*scale | k | v] = LN(lat) @ [Wq*0.125 | Wkv] + bcat
    gemm_tf32<<<dim3(12, 4, 1), 256, GEMM_SMEM>>>(
        lat, (const float2*)psl, g_l, b_l,
        (const uint32_t*)pwcat, (const float*)pbcat,
        (float*)plp, 1536, 512, nullptr);

    // media KV (mask-skipped)
    gemm_tf32<<<dim3(8, 64, 8), 256, GEMM_SMEM>>>(
        x, (const float2*)psm, g_m, b_m,
        (const uint32_t*)pwcat + 512 * 512, bkv,
        (float*)pkvmed, 1024, NMEDIA, idx);

    // attention
    attn_split_tc<<<dim3(NSPLIT, HEADS, BATCH), 128, ATTN_SMEM>>>(
        (const float*)plp, idx);
    attn_combine<<<dim3(64, 8), 256>>>(idx, (float*)pattno);

    // output projection
    gemm_tf32<<<dim3(4, 4, 1), 256, GEMM_SMEM>>>(
        (const float*)pattno, nullptr, nullptr, nullptr,
        (const uint32_t*)pwo, bo, out, 512, 512, nullptr);
}

// round 5
// speedup vs baseline: 3.8247x; 1.0528x over previous
#include <cuda_runtime.h>
#include <math_constants.h>
#include <cstdint>
#include <cstddef>

// ---------------------------------------------------------------------------
// Problem constants
// ---------------------------------------------------------------------------
#define BATCH   8
#define NMEDIA  8192
#define SLAT    64
#define HEADS   8
#define NSPLIT  33

// ---------------------------------------------------------------------------
// Scratch (device globals)
// ---------------------------------------------------------------------------
__device__ float    g_latproj[(size_t)512 * 1536];                  // [q | k | v]
__device__ float    g_kvmed [(size_t)BATCH * NMEDIA * 1024];
__device__ float    g_opart [(size_t)64 * NSPLIT * 64 * 64];
__device__ float    g_mpart [(size_t)64 * NSPLIT * 64];
__device__ float    g_lpart [(size_t)64 * NSPLIT * 64];
__device__ float    g_attno [(size_t)512 * 512];
__device__ uint32_t g_Wlat  [(size_t)1536 * 512];   // [0.125*g_l*Wq | g_l*Wkv]^T tf32
__device__ uint32_t g_Wmed  [(size_t)1024 * 512];   // [g_m*Wkv]^T tf32
__device__ uint32_t g_WoT   [(size_t)512 * 512];    // Wo^T tf32
__device__ float    g_c1lat[1536], g_c2lat[1536];
__device__ float    g_c1med[1024], g_c2med[1024];

// ---------------------------------------------------------------------------
// Helpers
// ---------------------------------------------------------------------------
__device__ __forceinline__ uint32_t f2tf32(float x) {
    uint32_t r;
    asm("cvt.rna.tf32.f32 %0, %1;" : "=r"(r) : "f"(x));
    return r;
}

__device__ __forceinline__ void mma_tf32(float* c, const uint32_t* a, const uint32_t* b) {
    asm volatile(
        "mma.sync.aligned.m16n8k8.row.col.f32.tf32.tf32.f32 "
        "{%0,%1,%2,%3},{%4,%5,%6,%7},{%8,%9},{%0,%1,%2,%3};"
        : "+f"(c[0]), "+f"(c[1]), "+f"(c[2]), "+f"(c[3])
        : "r"(a[0]), "r"(a[1]), "r"(a[2]), "r"(a[3]), "r"(b[0]), "r"(b[1]));
}

__device__ __forceinline__ void cp16(void* smem, const void* gmem) {
    uint32_t a = (uint32_t)__cvta_generic_to_shared(smem);
    asm volatile("cp.async.cg.shared.global [%0], [%1], 16;" :: "r"(a), "l"(gmem));
}
#define CP_COMMIT() asm volatile("cp.async.commit_group;")
#define CP_WAIT0()  asm volatile("cp.async.wait_group 0;")

// ---------------------------------------------------------------------------
// Weight prep: transpose + g-fold + scale-fold + tf32 convert.
//  z=0: 0.125*g_l*Wq -> Wlat[0:512]    z=1: g_l*Wkv -> Wlat[512:1536]
//  z=2: g_m*Wkv -> Wmed                z=3: Wo -> WoT
// ---------------------------------------------------------------------------
__global__ void __launch_bounds__(256)
prep_w(const float* __restrict__ Wq, const float* __restrict__ Wkv,
       const float* __restrict__ Wo, const float* __restrict__ gl,
       const float* __restrict__ gm)
{
    const float* W; uint32_t* WT; const float* gv; int nc; float scale = 1.f;
    switch (blockIdx.z) {
        case 0:  W = Wq;  WT = g_Wlat;             gv = gl;      nc = 512;  scale = 0.125f; break;
        case 1:  W = Wkv; WT = g_Wlat + 512 * 512; gv = gl;      nc = 1024; break;
        case 2:  W = Wkv; WT = g_Wmed;             gv = gm;      nc = 1024; break;
        default: W = Wo;  WT = g_WoT;              gv = nullptr; nc = 512;  break;
    }
    const int c0 = blockIdx.x * 64;
    if (c0 >= nc) return;
    const int k0 = blockIdx.y * 64;
    const int tid = threadIdx.x;

    __shared__ float ts[64][65];
    #pragma unroll
    for (int it = 0; it < 16; ++it) {
        int e = tid + it * 256;
        int k = e >> 6, c = e & 63;
        float gk = gv ? gv[k0 + k] * scale : scale;
        ts[k][c] = W[(size_t)(k0 + k) * nc + c0 + c] * gk;
    }
    __syncthreads();
    #pragma unroll
    for (int it = 0; it < 16; ++it) {
        int e = tid + it * 256;
        int c = e >> 6, k = e & 63;
        WT[(size_t)(c0 + c) * 512 + k0 + k] = f2tf32(ts[k][c]);
    }
}

// ---------------------------------------------------------------------------
// Column-vector prep: c1[c] = colsum of folded tf32 weights (exact w.r.t MMA),
// c2[c] = dot(b_ln, W_raw[:,c])*scale + bias[c]*scale.
// Blocks 0..23: latent cols (q scaled); blocks 24..39: media cols.
// ---------------------------------------------------------------------------
__global__ void __launch_bounds__(256)
prep_c(const float* __restrict__ Wq, const float* __restrict__ Wkv,
       const float* __restrict__ bq, const float* __restrict__ bkv,
       const float* __restrict__ bl, const float* __restrict__ bm)
{
    const int bx = blockIdx.x;
    const float *W, *bv, *bias;
    const uint32_t* WT;
    float *c1o, *c2o;
    int nc, srcCol, colBase;
    float scale = 1.f;

    if (bx < 24) {                      // latent config
        colBase = bx * 64;
        if (colBase < 512) { W = Wq;  nc = 512;  bias = bq;  srcCol = colBase;       scale = 0.125f; }
        else               { W = Wkv; nc = 1024; bias = bkv; srcCol = colBase - 512; }
        bv = bl; WT = g_Wlat; c1o = g_c1lat; c2o = g_c2lat;
    } else {                            // media config
        colBase = (bx - 24) * 64;
        W = Wkv; nc = 1024; bias = bkv; srcCol = colBase;
        bv = bm; WT = g_Wmed; c1o = g_c1med; c2o = g_c2med;
    }

    const int tid = threadIdx.x;
    // ---- c2 ----
    {
        const int c = tid & 63, kq = tid >> 6;
        float part = 0.f;
        for (int k = kq; k < 512; k += 4)
            part = fmaf(bv[k], W[(size_t)k * nc + srcCol + c], part);
        __shared__ float red[4][64];
        red[kq][c] = part;
        __syncthreads();
        if (tid < 64) {
            float s = red[0][tid] + red[1][tid] + red[2][tid] + red[3][tid];
            c2o[colBase + tid] = (s + bias[srcCol + tid]) * scale;
        }
    }
    // ---- c1 (colsum of tf32 folded weights) ----
    {
        const int warp = tid >> 5, lane = tid & 31;
        #pragma unroll
        for (int cc = 0; cc < 8; ++cc) {
            int col = colBase + warp * 8 + cc;
            const uint32_t* p = WT + (size_t)col * 512;
            float s = 0.f;
            #pragma unroll
            for (int u = 0; u < 16; ++u)
                s += __uint_as_float(p[lane + 32 * u]);
            #pragma unroll
            for (int o = 16; o > 0; o >>= 1)
                s += __shfl_xor_sync(0xffffffffu, s, o);
            if (lane == 0) c1o[col] = s;
        }
    }
}

// ---------------------------------------------------------------------------
// Big GEMM: 128x256 tile, 256 threads (8 warps, 2x4, warp tile 64x64),
// double-buffered (B cp.async, A register prefetch), in-kernel LN stats,
// epilogue LN:  out = rs*acc - rs*mu*c1 + c2.
// Unified grid: blocks [0,2048) media KV (mask-skipped), [2048,2072) latproj.
// ---------------------------------------------------------------------------
__global__ void __launch_bounds__(256, 1)
gemm_big(const float* __restrict__ x, const float* __restrict__ lat,
         const int* __restrict__ idx)
{
    const int bid = blockIdx.x;
    const float* src; const uint32_t* WT; float* out;
    const float *c1, *c2;
    int nc;
    if (bid < 2048) {
        const int b = bid >> 8, rr = (bid >> 2) & 63, cc = bid & 3;
        const int rowBase = rr * 128;
        if (rowBase >= idx[b] * 256) return;
        src = x + ((size_t)b * NMEDIA + rowBase) * 512;
        WT  = g_Wmed + (size_t)(cc * 256) * 512;
        out = g_kvmed + ((size_t)b * NMEDIA + rowBase) * 1024 + cc * 256;
        c1 = g_c1med + cc * 256; c2 = g_c2med + cc * 256;
        nc = 1024;
    } else {
        const int l = bid - 2048;        // 0..23
        const int rr = l / 6, cc = l % 6;
        src = lat + (size_t)(rr * 128) * 512;
        WT  = g_Wlat + (size_t)(cc * 256) * 512;
        out = g_latproj + (size_t)(rr * 128) * 1536 + cc * 256;
        c1 = g_c1lat + cc * 256; c2 = g_c2lat + cc * 256;
        nc = 1536;
    }

    extern __shared__ uint32_t dyn[];
    uint32_t* As = dyn;                  // [2][128*36]
    uint32_t* Bs = dyn + 2 * 4608;       // [2][256*36]
    __shared__ float2 st[128];

    const int tid = threadIdx.x;
    const int am = tid >> 3, akq = (tid & 7) * 4;

    float4 rv[4];
    float sm[4] = {0.f, 0.f, 0.f, 0.f};
    float sq[4] = {0.f, 0.f, 0.f, 0.f};

    auto lda = [&](int k0) {
        #pragma unroll
        for (int u = 0; u < 4; ++u)
            rv[u] = *(const float4*)(src + (size_t)(am + 32 * u) * 512 + k0 + akq);
    };
    auto sta = [&](int buf) {
        #pragma unroll
        for (int u = 0; u < 4; ++u) {
            float4 v = rv[u];
            sm[u] += v.x + v.y + v.z + v.w;
            sq[u] = fmaf(v.x, v.x, sq[u]); sq[u] = fmaf(v.y, v.y, sq[u]);
            sq[u] = fmaf(v.z, v.z, sq[u]); sq[u] = fmaf(v.w, v.w, sq[u]);
            uint4 t;
            t.x = f2tf32(v.x); t.y = f2tf32(v.y);
            t.z = f2tf32(v.z); t.w = f2tf32(v.w);
            *(uint4*)&As[buf * 4608 + (am + 32 * u) * 36 + akq] = t;
        }
    };
    auto cpb = [&](int k0, int buf) {
        #pragma unroll
        for (int u = 0; u < 8; ++u) {
            int c = am + 32 * u;
            cp16(&Bs[buf * 9216 + c * 36 + akq],
                 WT + (size_t)c * 512 + k0 + akq);
        }
        CP_COMMIT();
    };

    const int warp = tid >> 5, lane = tid & 31;
    const int wm = warp >> 2, wn = warp & 3;
    const int qr = lane >> 2, qc = lane & 3;

    float acc[4][8][4];
    #pragma unroll
    for (int i = 0; i < 4; ++i)
        #pragma unroll
        for (int j = 0; j < 8; ++j)
            #pragma unroll
            for (int r = 0; r < 4; ++r) acc[i][j][r] = 0.f;

    lda(0); sta(0); cpb(0, 0);

    for (int kc = 0; kc < 16; ++kc) {
        const int buf = kc & 1;
        CP_WAIT0();
        __syncthreads();

        const bool nxt = (kc < 15);
        if (nxt) { lda((kc + 1) * 32); cpb((kc + 1) * 32, buf ^ 1); }

        const uint32_t* Ab = As + buf * 4608;
        const uint32_t* Bb = Bs + buf * 9216;
        #pragma unroll
        for (int ks = 0; ks < 4; ++ks) {
            uint32_t a[4][4], bb[8][2];
            #pragma unroll
            for (int i = 0; i < 4; ++i) {
                int r0 = wm * 64 + i * 16 + qr;
                a[i][0] = Ab[(r0    ) * 36 + ks * 8 + qc    ];
                a[i][1] = Ab[(r0 + 8) * 36 + ks * 8 + qc    ];
                a[i][2] = Ab[(r0    ) * 36 + ks * 8 + qc + 4];
                a[i][3] = Ab[(r0 + 8) * 36 + ks * 8 + qc + 4];
            }
            #pragma unroll
            for (int j = 0; j < 8; ++j) {
                int cb = wn * 64 + j * 8 + qr;
                bb[j][0] = Bb[cb * 36 + ks * 8 + qc    ];
                bb[j][1] = Bb[cb * 36 + ks * 8 + qc + 4];
            }
            #pragma unroll
            for (int i = 0; i < 4; ++i)
                #pragma unroll
                for (int j = 0; j < 8; ++j)
                    mma_tf32(acc[i][j], a[i], bb[j]);
        }

        if (nxt) sta(buf ^ 1);
    }

    // ---- LN stats reduce (8-lane groups share a row set) ----
    #pragma unroll
    for (int u = 0; u < 4; ++u) {
        #pragma unroll
        for (int o = 1; o < 8; o <<= 1) {
            sm[u] += __shfl_xor_sync(0xffffffffu, sm[u], o);
            sq[u] += __shfl_xor_sync(0xffffffffu, sq[u], o);
        }
    }
    if ((tid & 7) == 0) {
        #pragma unroll
        for (int u = 0; u < 4; ++u) {
            float mu  = sm[u] * (1.f / 512.f);
            float var = fmaf(-mu, mu, sq[u] * (1.f / 512.f));
            st[am + 32 * u] = make_float2(mu, rsqrtf(var + 1e-5f));
        }
    }
    __syncthreads();

    // ---- epilogue: out = rs*acc - rs*mu*c1 + c2 ----
    #pragma unroll
    for (int i = 0; i < 4; ++i) {
        int r0 = wm * 64 + i * 16 + qr;
        float2 s0 = st[r0], s1 = st[r0 + 8];
        float rs0 = s0.y, t0 = s0.y * s0.x;
        float rs1 = s1.y, t1 = s1.y * s1.x;
        #pragma unroll
        for (int j = 0; j < 8; ++j) {
            int col = wn * 64 + j * 8 + qc * 2;
            float2 c1v = *(const float2*)(c1 + col);
            float2 c2v = *(const float2*)(c2 + col);
            float2 o0, o1;
            o0.x = fmaf(acc[i][j][0], rs0, fmaf(-t0, c1v.x, c2v.x));
            o0.y = fmaf(acc[i][j][1], rs0, fmaf(-t0, c1v.y, c2v.y));
            o1.x = fmaf(acc[i][j][2], rs1, fmaf(-t1, c1v.x, c2v.x));
            o1.y = fmaf(acc[i][j][3], rs1, fmaf(-t1, c1v.y, c2v.y));
            *(float2*)(out + (size_t)(r0    ) * nc + col) = o0;
            *(float2*)(out + (size_t)(r0 + 8) * nc + col) = o1;
        }
    }
}
#define BIG_SMEM ((2 * 4608 + 2 * 9216) * (int)sizeof(uint32_t))

// ---------------------------------------------------------------------------
// Output projection GEMM: 128x128 tile, 256 threads, double-buffered, no LN.
// (R4 bug fixed: full 128-row/128-col staging, u<4 with stride-32 rows.)
// ---------------------------------------------------------------------------
__global__ void __launch_bounds__(256, 2)
gemm_out(const float* __restrict__ src, const float* __restrict__ bias,
         float* __restrict__ out)
{
    const int rowBase = (blockIdx.x >> 2) * 128;
    const int colBase = (blockIdx.x & 3) * 128;
    const float* srcB = src + (size_t)rowBase * 512;
    float* outB = out + (size_t)rowBase * 512;

    extern __shared__ uint32_t dyn2[];
    uint32_t* As = dyn2;                 // [2][128*36]
    uint32_t* Bs = dyn2 + 2 * 4608;      // [2][128*36]

    const int tid = threadIdx.x;
    const int am = tid >> 3, akq = (tid & 7) * 4;
    float4 rv[4];

    auto lda = [&](int k0) {
        #pragma unroll
        for (int u = 0; u < 4; ++u)
            rv[u] = *(const float4*)(srcB + (size_t)(am + 32 * u) * 512 + k0 + akq);
    };
    auto sta = [&](int buf) {
        #pragma unroll
        for (int u = 0; u < 4; ++u) {
            float4 v = rv[u];
            uint4 t;
            t.x = f2tf32(v.x); t.y = f2tf32(v.y);
            t.z = f2tf32(v.z); t.w = f2tf32(v.w);
            *(uint4*)&As[buf * 4608 + (am + 32 * u) * 36 + akq] = t;
        }
    };
    auto cpb = [&](int k0, int buf) {
        #pragma unroll
        for (int u = 0; u < 4; ++u) {
            int c = am + 32 * u;
            cp16(&Bs[buf * 4608 + c * 36 + akq],
                 g_WoT + (size_t)(colBase + c) * 512 + k0 + akq);
        }
        CP_COMMIT();
    };

    const int warp = tid >> 5, lane = tid & 31;
    const int wm = warp >> 2, wn = warp & 3;
    const int qr = lane >> 2, qc = lane & 3;

    float acc[4][4][4];
    #pragma unroll
    for (int i = 0; i < 4; ++i)
        #pragma unroll
        for (int j = 0; j < 4; ++j)
            #pragma unroll
            for (int r = 0; r < 4; ++r) acc[i][j][r] = 0.f;

    lda(0); sta(0); cpb(0, 0);

    for (int kc = 0; kc < 16; ++kc) {
        const int buf = kc & 1;
        CP_WAIT0();
        __syncthreads();
        const bool nxt = (kc < 15);
        if (nxt) { lda((kc + 1) * 32); cpb((kc + 1) * 32, buf ^ 1); }

        const uint32_t* Ab = As + buf * 4608;
        const uint32_t* Bb = Bs + buf * 4608;
        #pragma unroll
        for (int ks = 0; ks < 4; ++ks) {
            uint32_t a[4][4], bb[4][2];
            #pragma unroll
            for (int i = 0; i < 4; ++i) {
                int r0 = wm * 64 + i * 16 + qr;
                a[i][0] = Ab[(r0    ) * 36 + ks * 8 + qc    ];
                a[i][1] = Ab[(r0 + 8) * 36 + ks * 8 + qc    ];
                a[i][2] = Ab[(r0    ) * 36 + ks * 8 + qc + 4];
                a[i][3] = Ab[(r0 + 8) * 36 + ks * 8 + qc + 4];
            }
            #pragma unroll
            for (int j = 0; j < 4; ++j) {
                int cb = wn * 32 + j * 8 + qr;
                bb[j][0] = Bb[cb * 36 + ks * 8 + qc    ];
                bb[j][1] = Bb[cb * 36 + ks * 8 + qc + 4];
            }
            #pragma unroll
            for (int i = 0; i < 4; ++i)
                #pragma unroll
                for (int j = 0; j < 4; ++j)
                    mma_tf32(acc[i][j], a[i], bb[j]);
        }
        if (nxt) sta(buf ^ 1);
    }

    #pragma unroll
    for (int i = 0; i < 4; ++i) {
        int r0 = wm * 64 + i * 16 + qr;
        #pragma unroll
        for (int j = 0; j < 4; ++j) {
            int col = colBase + wn * 32 + j * 8 + qc * 2;
            float2 bi = *(const float2*)(bias + col);
            *(float2*)(outB + (size_t)(r0    ) * 512 + col) =
                make_float2(acc[i][j][0] + bi.x, acc[i][j][1] + bi.y);
            *(float2*)(outB + (size_t)(r0 + 8) * 512 + col) =
                make_float2(acc[i][j][2] + bi.x, acc[i][j][3] + bi.y);
        }
    }
}
#define OUT_SMEM (4 * 4608 * (int)sizeof(uint32_t))

// ---------------------------------------------------------------------------
// Tensor-core split-KV flash attention (as R3, passing).
// ---------------------------------------------------------------------------
__global__ void __launch_bounds__(128)
attn_split_tc(const float* __restrict__ latproj, const int* __restrict__ indices)
{
    const int b = blockIdx.z, h = blockIdx.y, s = blockIdx.x;
    const int vis = indices[b];
    const bool is_lat = (s == 32);
    if (!is_lat && s >= vis) return;

    extern __shared__ float smf[];
    float*    Ks = smf;                              // [64][72]
    float*    Vs = Ks + 64 * 72;                     // [64][72]
    uint32_t* Qs = (uint32_t*)(Vs + 64 * 72);        // [64][68]
    uint32_t* Ps = Qs + 64 * 68;                     // [64][68]

    const int tid = threadIdx.x, warp = tid >> 5, lane = tid & 31;
    const int qr = lane >> 2, qc = lane & 3;
    const int r0 = warp * 16 + qr;

    #pragma unroll
    for (int it = 0; it < 8; ++it) {
        int e = tid + it * 128;
        int r = e >> 4, cq = (e & 15) * 4;
        float4 v = *(const float4*)(latproj + ((size_t)b * 64 + r) * 1536 + h * 64 + cq);
        uint4 t;
        t.x = f2tf32(v.x); t.y = f2tf32(v.y);
        t.z = f2tf32(v.z); t.w = f2tf32(v.w);
        *(uint4*)&Qs[r * 68 + cq] = t;
    }

    const float* kvbase; int ldkv, koff, voff, nch;
    if (is_lat) {
        kvbase = latproj + (size_t)b * 64 * 1536;
        ldkv = 1536; koff = 512 + h * 64; voff = 1024 + h * 64; nch = 1;
    } else {
        kvbase = g_kvmed + ((size_t)b * NMEDIA + (size_t)s * 256) * 1024;
        ldkv = 1024; koff = h * 64; voff = 512 + h * 64; nch = 4;
    }

    float m0 = -CUDART_INF_F, m1 = -CUDART_INF_F, l0 = 0.f, l1 = 0.f;
    float o[8][4];
    #pragma unroll
    for (int nf = 0; nf < 8; ++nf)
        #pragma unroll
        for (int r = 0; r < 4; ++r) o[nf][r] = 0.f;

    for (int ch = 0; ch < nch; ++ch) {
        __syncthreads();
        #pragma unroll
        for (int it = 0; it < 8; ++it) {
            int e = tid + it * 128;
            int j = e >> 4, dq = (e & 15) * 4;
            const float* rp = kvbase + (size_t)(ch * 64 + j) * ldkv;
            float4 kv = *(const float4*)(rp + koff + dq);
            float4 vv = *(const float4*)(rp + voff + dq);
            uint32_t* kd = (uint32_t*)&Ks[j * 72 + dq];
            kd[0] = f2tf32(kv.x); kd[1] = f2tf32(kv.y);
            kd[2] = f2tf32(kv.z); kd[3] = f2tf32(kv.w);
            uint32_t* vd = (uint32_t*)&Vs[j * 72 + dq];
            vd[0] = f2tf32(vv.x); vd[1] = f2tf32(vv.y);
            vd[2] = f2tf32(vv.z); vd[3] = f2tf32(vv.w);
        }
        __syncthreads();

        float sacc[8][4] = {};
        const uint32_t* Ku = (const uint32_t*)Ks;
        #pragma unroll
        for (int ks = 0; ks < 8; ++ks) {
            uint32_t a[4];
            a[0] = Qs[(r0    ) * 68 + ks * 8 + qc    ];
            a[1] = Qs[(r0 + 8) * 68 + ks * 8 + qc    ];
            a[2] = Qs[(r0    ) * 68 + ks * 8 + qc + 4];
            a[3] = Qs[(r0 + 8) * 68 + ks * 8 + qc + 4];
            #pragma unroll
            for (int nf = 0; nf < 8; ++nf) {
                uint32_t bb[2];
                bb[0] = Ku[(nf * 8 + qr) * 72 + ks * 8 + qc    ];
                bb[1] = Ku[(nf * 8 + qr) * 72 + ks * 8 + qc + 4];
                mma_tf32(sacc[nf], a, bb);
            }
        }

        float rm0 = -CUDART_INF_F, rm1 = -CUDART_INF_F;
        #pragma unroll
        for (int nf = 0; nf < 8; ++nf) {
            rm0 = fmaxf(rm0, fmaxf(sacc[nf][0], sacc[nf][1]));
            rm1 = fmaxf(rm1, fmaxf(sacc[nf][2], sacc[nf][3]));
        }
        rm0 = fmaxf(rm0, __shfl_xor_sync(0xffffffffu, rm0, 1));
        rm0 = fmaxf(rm0, __shfl_xor_sync(0xffffffffu, rm0, 2));
        rm1 = fmaxf(rm1, __shfl_xor_sync(0xffffffffu, rm1, 1));
        rm1 = fmaxf(rm1, __shfl_xor_sync(0xffffffffu, rm1, 2));
        float mn0 = fmaxf(m0, rm0), mn1 = fmaxf(m1, rm1);
        float cc0 = __expf(m0 - mn0), cc1 = __expf(m1 - mn1);
        float s0 = 0.f, s1 = 0.f;
        #pragma unroll
        for (int nf = 0; nf < 8; ++nf) {
            float p00 = __expf(sacc[nf][0] - mn0);
            float p01 = __expf(sacc[nf][1] - mn0);
            float p10 = __expf(sacc[nf][2] - mn1);
            float p11 = __expf(sacc[nf][3] - mn1);
            s0 += p00 + p01; s1 += p10 + p11;
            *(uint2*)&Ps[(r0    ) * 68 + nf * 8 + qc * 2] =
                make_uint2(f2tf32(p00), f2tf32(p01));
            *(uint2*)&Ps[(r0 + 8) * 68 + nf * 8 + qc * 2] =
                make_uint2(f2tf32(p10), f2tf32(p11));
            o[nf][0] *= cc0; o[nf][1] *= cc0;
            o[nf][2] *= cc1; o[nf][3] *= cc1;
        }
        s0 += __shfl_xor_sync(0xffffffffu, s0, 1);
        s0 += __shfl_xor_sync(0xffffffffu, s0, 2);
        s1 += __shfl_xor_sync(0xffffffffu, s1, 1);
        s1 += __shfl_xor_sync(0xffffffffu, s1, 2);
        m0 = mn0; m1 = mn1;
        l0 = fmaf(l0, cc0, s0);
        l1 = fmaf(l1, cc1, s1);
        __syncwarp();

        const uint32_t* Vu = (const uint32_t*)Vs;
        #pragma unroll
        for (int ks = 0; ks < 8; ++ks) {
            uint32_t a[4];
            a[0] = Ps[(r0    ) * 68 + ks * 8 + qc    ];
            a[1] = Ps[(r0 + 8) * 68 + ks * 8 + qc    ];
            a[2] = Ps[(r0    ) * 68 + ks * 8 + qc + 4];
            a[3] = Ps[(r0 + 8) * 68 + ks * 8 + qc + 4];
            #pragma unroll
            for (int nf = 0; nf < 8; ++nf) {
                uint32_t bb[2];
                bb[0] = Vu[(ks * 8 + qc    ) * 72 + nf * 8 + qr];
                bb[1] = Vu[(ks * 8 + qc + 4) * 72 + nf * 8 + qr];
                mma_tf32(o[nf], a, bb);
            }
        }
    }

    const size_t pbase = ((size_t)(b * HEADS + h)) * NSPLIT + s;
    float* op = g_opart + pbase * 4096;
    #pragma unroll
    for (int nf = 0; nf < 8; ++nf) {
        *(float2*)&op[(r0    ) * 64 + nf * 8 + qc * 2] = make_float2(o[nf][0], o[nf][1]);
        *(float2*)&op[(r0 + 8) * 64 + nf * 8 + qc * 2] = make_float2(o[nf][2], o[nf][3]);
    }
    if (qc == 0) {
        g_mpart[pbase * 64 + r0    ] = m0;
        g_mpart[pbase * 64 + r0 + 8] = m1;
        g_lpart[pbase * 64 + r0    ] = l0;
        g_lpart[pbase * 64 + r0 + 8] = l1;
    }
}
#define ATTN_SMEM ((2 * 64 * 72 + 2 * 64 * 68) * (int)sizeof(float))

// ---------------------------------------------------------------------------
// Combine split partials -> attn_out.
// ---------------------------------------------------------------------------
__global__ void __launch_bounds__(256)
attn_combine(const int* __restrict__ indices, float* __restrict__ attn_out)
{
    const int bh = blockIdx.x;
    const int b = bh >> 3, h = bh & 7;
    const int vis = indices[b];
    const int warp = threadIdx.x >> 5, lane = threadIdx.x & 31;
    const int i = blockIdx.y * 8 + warp;

    __shared__ float ws[8][33];
    __shared__ float linv[8];

    const size_t base = (size_t)bh * NSPLIT;

    float m    = (lane < vis) ? g_mpart[(base + lane) * 64 + i] : -CUDART_INF_F;
    float mlat = g_mpart[(base + 32) * 64 + i];
    float mm = fmaxf(m, mlat);
    #pragma unroll
    for (int o = 16; o > 0; o >>= 1)
        mm = fmaxf(mm, __shfl_xor_sync(0xffffffffu, mm, o));

    float w  = (lane < vis) ? __expf(m - mm) : 0.f;
    float wl = __expf(mlat - mm);
    float l  = (lane < vis) ? g_lpart[(base + lane) * 64 + i] * w : 0.f;
    #pragma unroll
    for (int o = 16; o > 0; o >>= 1)
        l += __shfl_xor_sync(0xffffffffu, l, o);
    float ll = g_lpart[(base + 32) * 64 + i] * wl;

    ws[warp][lane] = w;
    if (lane == 0) {
        ws[warp][32] = wl;
        linv[warp] = 1.f / (l + ll);
    }
    __syncwarp();

    const int d = lane * 2;
    float2 v = *(const float2*)(g_opart + (base + 32) * 4096 + i * 64 + d);
    float a0 = v.x * ws[warp][32];
    float a1 = v.y * ws[warp][32];
    for (int s = 0; s < vis; ++s) {
        float wv = ws[warp][s];
        float2 u = *(const float2*)(g_opart + (base + s) * 4096 + i * 64 + d);
        a0 = fmaf(u.x, wv, a0);
        a1 = fmaf(u.y, wv, a1);
    }
    float li = linv[warp];
    *(float2*)(attn_out + ((size_t)b * 64 + i) * 512 + h * 64 + d) =
        make_float2(a0 * li, a1 * li);
}

// ---------------------------------------------------------------------------
// Launch
// ---------------------------------------------------------------------------
extern "C" void kernel_launch(void* const* d_in, const int* in_sizes, int n_in,
                              void* d_out, int out_size)
{
    (void)in_sizes; (void)n_in; (void)out_size;
    const float* x    = (const float*)d_in[0];
    const float* lat  = (const float*)d_in[1];
    const int*   idx  = (const int*)  d_in[2];
    const float* g_m  = (const float*)d_in[3];
    const float* b_m  = (const float*)d_in[4];
    const float* g_l  = (const float*)d_in[5];
    const float* b_l  = (const float*)d_in[6];
    const float* Wq   = (const float*)d_in[7];
    const float* bq   = (const float*)d_in[8];
    const float* Wkv  = (const float*)d_in[9];
    const float* bkv  = (const float*)d_in[10];
    const float* Wo   = (const float*)d_in[11];
    const float* bo   = (const float*)d_in[12];
    float* out = (float*)d_out;

    void *plp, *pattno;
    cudaGetSymbolAddress(&plp,    g_latproj);
    cudaGetSymbolAddress(&pattno, g_attno);

    cudaFuncSetAttribute(gemm_big,
                         cudaFuncAttributeMaxDynamicSharedMemorySize, BIG_SMEM);
    cudaFuncSetAttribute(gemm_out,
                         cudaFuncAttributeMaxDynamicSharedMemorySize, OUT_SMEM);
    cudaFuncSetAttribute(attn_split_tc,
                         cudaFuncAttributeMaxDynamicSharedMemorySize, ATTN_SMEM);

    // weight + column-vector prep
    prep_w<<<dim3(16, 8, 4), 256>>>(Wq, Wkv, Wo, g_l, g_m);
    prep_c<<<40, 256>>>(Wq, Wkv, bq, bkv, b_l, b_m);

    // unified media-KV + latent projections (LN fused via epilogue)
    gemm_big<<<2072, 256, BIG_SMEM>>>(x, lat, idx);

    // attention
    attn_split_tc<<<dim3(NSPLIT, HEADS, BATCH), 128, ATTN_SMEM>>>(
        (const float*)plp, idx);
    attn_combine<<<dim3(64, 8), 256>>>(idx, (float*)pattno);

    // output projection
    gemm_out<<<16, 256, OUT_SMEM>>>((const float*)pattno, bo, out);
}